// round 1
// baseline (speedup 1.0000x reference)
#include <cuda_runtime.h>
#include <math.h>

// ---------------- static config ----------------
#define BATCH 24
#define HH 60
#define WW 60
#define HP 63
#define WSZ 7
#define SSZ 3
#define NWIN 81          // 9x9 windows
#define NTOK 49          // tokens per window
#define DIM 256
#define NHEAD 8
#define HD 32
#define MW (BATCH*NWIN*NTOK)   // 95256 window tokens
#define MT (BATCH*HH*WW)       // 86400 real tokens

// ---------------- scratch (static device globals; no allocation) ----------------
__device__ float g_xw[(size_t)MW*DIM];        // LN1 + windowed input; reused as proj output
__device__ float g_qkv[(size_t)MW*3*DIM];     // qkv
__device__ float g_att[(size_t)MW*DIM];       // attention output (window layout)
__device__ float g_x1[(size_t)MT*DIM];        // x + attn branch
__device__ float g_y [(size_t)MT*DIM];        // LN2 output
__device__ float g_h [(size_t)MT*4*DIM];      // fc1 output

// ---------------- helpers ----------------
__device__ __forceinline__ float warp_sum(float v) {
    #pragma unroll
    for (int o = 16; o; o >>= 1) v += __shfl_xor_sync(0xffffffffu, v, o);
    return v;
}

__device__ __forceinline__ int region_label(int p) {   // position in padded 63 grid
    return p < (HP - WSZ) ? 0 : (p < (HP - SSZ) ? 1 : 2);
}

// ---------------- LN1 + pad + shift + window partition ----------------
// one warp per window token; pad tokens -> zeros (reference pads AFTER LN)
__global__ __launch_bounds__(256) void ln1_window_kernel(
    const float* __restrict__ x, const float* __restrict__ g, const float* __restrict__ b)
{
    int warp = (blockIdx.x * blockDim.x + threadIdx.x) >> 5;
    int lane = threadIdx.x & 31;
    if (warp >= MW) return;
    int bi  = warp / (NWIN*NTOK);
    int rem = warp - bi*(NWIN*NTOK);
    int w = rem / NTOK, n = rem - w*NTOK;
    int r = w/9, c = w - r*9, i = n/7, j = n - i*7;
    int hs = r*7 + i + SSZ; if (hs >= HP) hs -= HP;
    int ws = c*7 + j + SSZ; if (ws >= HP) ws -= HP;

    float4* dst = (float4*)(g_xw + (size_t)warp*DIM);
    if (hs >= HH || ws >= WW) {
        float4 z = make_float4(0.f,0.f,0.f,0.f);
        dst[lane] = z; dst[lane+32] = z;
        return;
    }
    const float4* src = (const float4*)(x + ((size_t)bi*(HH*WW) + hs*WW + ws)*DIM);
    float4 v0 = src[lane], v1 = src[lane+32];
    float s  = v0.x+v0.y+v0.z+v0.w + v1.x+v1.y+v1.z+v1.w;
    float ss = v0.x*v0.x+v0.y*v0.y+v0.z*v0.z+v0.w*v0.w
             + v1.x*v1.x+v1.y*v1.y+v1.z*v1.z+v1.w*v1.w;
    s  = warp_sum(s);
    ss = warp_sum(ss);
    float mu   = s * (1.f/DIM);
    float var  = ss * (1.f/DIM) - mu*mu;
    float rstd = rsqrtf(var + 1e-5f);
    const float4* gv = (const float4*)g;
    const float4* bv = (const float4*)b;
    float4 g0 = gv[lane], g1 = gv[lane+32], b0 = bv[lane], b1 = bv[lane+32];
    float4 o0, o1;
    o0.x = (v0.x-mu)*rstd*g0.x + b0.x;  o0.y = (v0.y-mu)*rstd*g0.y + b0.y;
    o0.z = (v0.z-mu)*rstd*g0.z + b0.z;  o0.w = (v0.w-mu)*rstd*g0.w + b0.w;
    o1.x = (v1.x-mu)*rstd*g1.x + b1.x;  o1.y = (v1.y-mu)*rstd*g1.y + b1.y;
    o1.z = (v1.z-mu)*rstd*g1.z + b1.z;  o1.w = (v1.w-mu)*rstd*g1.w + b1.w;
    dst[lane] = o0; dst[lane+32] = o1;
}

// ---------------- LN2 (plain rows) ----------------
__global__ __launch_bounds__(256) void ln2_kernel(
    const float* __restrict__ g, const float* __restrict__ b)
{
    int warp = (blockIdx.x * blockDim.x + threadIdx.x) >> 5;
    int lane = threadIdx.x & 31;
    if (warp >= MT) return;
    const float4* src = (const float4*)(g_x1 + (size_t)warp*DIM);
    float4* dst = (float4*)(g_y + (size_t)warp*DIM);
    float4 v0 = src[lane], v1 = src[lane+32];
    float s  = v0.x+v0.y+v0.z+v0.w + v1.x+v1.y+v1.z+v1.w;
    float ss = v0.x*v0.x+v0.y*v0.y+v0.z*v0.z+v0.w*v0.w
             + v1.x*v1.x+v1.y*v1.y+v1.z*v1.z+v1.w*v1.w;
    s  = warp_sum(s);
    ss = warp_sum(ss);
    float mu   = s * (1.f/DIM);
    float var  = ss * (1.f/DIM) - mu*mu;
    float rstd = rsqrtf(var + 1e-5f);
    const float4* gv = (const float4*)g;
    const float4* bv = (const float4*)b;
    float4 g0 = gv[lane], g1 = gv[lane+32], b0 = bv[lane], b1 = bv[lane+32];
    float4 o0, o1;
    o0.x = (v0.x-mu)*rstd*g0.x + b0.x;  o0.y = (v0.y-mu)*rstd*g0.y + b0.y;
    o0.z = (v0.z-mu)*rstd*g0.z + b0.z;  o0.w = (v0.w-mu)*rstd*g0.w + b0.w;
    o1.x = (v1.x-mu)*rstd*g1.x + b1.x;  o1.y = (v1.y-mu)*rstd*g1.y + b1.y;
    o1.z = (v1.z-mu)*rstd*g1.z + b1.z;  o1.w = (v1.w-mu)*rstd*g1.w + b1.w;
    dst[lane] = o0; dst[lane+32] = o1;
}

// ---------------- SGEMM 128x128x8, 8x8/thread ----------------
// C[M,N] = A[M,K] @ B[K,N] (+bias[N]) (+GELU | +Res[M,N])
// N multiple of 128, K multiple of 8; M guarded.
#define EPI_BIAS 0
#define EPI_GELU 1
#define EPI_RES  2

template<int EPI>
__global__ __launch_bounds__(256) void sgemm_k(
    const float* __restrict__ A, const float* __restrict__ Bm,
    const float* __restrict__ bias, const float* __restrict__ Res,
    float* __restrict__ C, int M, int N, int K)
{
    __shared__ float As[8][132];
    __shared__ float Bs[8][128];
    const int tid = threadIdx.x;
    const int bm = blockIdx.y, bn = blockIdx.x;

    float acc[8][8];
    #pragma unroll
    for (int i = 0; i < 8; i++)
        #pragma unroll
        for (int j = 0; j < 8; j++) acc[i][j] = 0.f;

    const int arow = tid >> 1;             // 0..127
    const int acol = (tid & 1) << 2;       // 0|4
    const int brow = tid >> 5;             // 0..7
    const int bcol = (tid & 31) << 2;      // 0..124
    const int ra   = (tid >> 4) << 3;      // thread row base
    const int cb   = (tid & 15) << 3;      // thread col base

    const int gArow = bm*128 + arow;
    const bool avalid = gArow < M;
    const float* Aptr = A + (size_t)(avalid ? gArow : 0)*K + acol;
    const float* Bptr = Bm + (size_t)brow*N + bn*128 + bcol;

    for (int k0 = 0; k0 < K; k0 += 8) {
        float4 av = avalid ? *(const float4*)(Aptr + k0) : make_float4(0.f,0.f,0.f,0.f);
        float4 bv = *(const float4*)(Bptr + (size_t)k0*N);
        __syncthreads();
        As[acol+0][arow] = av.x;
        As[acol+1][arow] = av.y;
        As[acol+2][arow] = av.z;
        As[acol+3][arow] = av.w;
        *(float4*)&Bs[brow][bcol] = bv;
        __syncthreads();
        #pragma unroll
        for (int kk = 0; kk < 8; kk++) {
            float a[8], b[8];
            *(float4*)&a[0] = *(const float4*)&As[kk][ra];
            *(float4*)&a[4] = *(const float4*)&As[kk][ra+4];
            *(float4*)&b[0] = *(const float4*)&Bs[kk][cb];
            *(float4*)&b[4] = *(const float4*)&Bs[kk][cb+4];
            #pragma unroll
            for (int i = 0; i < 8; i++)
                #pragma unroll
                for (int j = 0; j < 8; j++)
                    acc[i][j] = fmaf(a[i], b[j], acc[i][j]);
        }
    }

    float bb[8];
    #pragma unroll
    for (int j = 0; j < 8; j++) bb[j] = bias[bn*128 + cb + j];

    #pragma unroll
    for (int i = 0; i < 8; i++) {
        int row = bm*128 + ra + i;
        if (row < M) {
            float* cp = C + (size_t)row*N + bn*128 + cb;
            const float* rp = (EPI == EPI_RES) ? (Res + (size_t)row*N + bn*128 + cb) : nullptr;
            #pragma unroll
            for (int j = 0; j < 8; j++) {
                float v = acc[i][j] + bb[j];
                if (EPI == EPI_GELU) v = 0.5f*v*(1.f + erff(v*0.70710678118654752f));
                if (EPI == EPI_RES)  v += rp[j];
                cp[j] = v;
            }
        }
    }
}

// ---------------- attention: one block per (window, head) ----------------
__global__ __launch_bounds__(128) void attn_kernel(const float* __restrict__ relt)
{
    __shared__ float Qs[NTOK][33];
    __shared__ float Ks[NTOK][33];
    __shared__ float Vs[NTOK][33];
    __shared__ float Ss[NTOK][50];

    const int tid = threadIdx.x;
    const int wh  = blockIdx.x;
    const int win = wh >> 3;      // 0..B*NWIN-1
    const int h   = wh & 7;

    const float* base = g_qkv + (size_t)win*NTOK*(3*DIM) + h*HD;
    const float scale = 0.17677669529663687f;   // 1/sqrt(32)
    for (int e = tid; e < NTOK*HD; e += 128) {
        int n = e >> 5, d = e & 31;
        const float* row = base + (size_t)n*(3*DIM);
        Qs[n][d] = row[d] * scale;
        Ks[n][d] = row[DIM + d];
        Vs[n][d] = row[2*DIM + d];
    }
    __syncthreads();

    const int w  = win % NWIN;
    const int wr = w / 9, wc = w - (w/9)*9;

    for (int e = tid; e < NTOK*NTOK; e += 128) {
        int n = e / NTOK, m = e - n*NTOK;
        float acc = 0.f;
        #pragma unroll
        for (int d = 0; d < HD; d++) acc = fmaf(Qs[n][d], Ks[m][d], acc);
        int in_ = n/7, jn = n - in_*7, im = m/7, jm = m - im*7;
        int idx = (in_ - im + 6)*13 + (jn - jm + 6);
        acc += __ldg(&relt[idx*NHEAD + h]);
        int rn = region_label(wr*7 + in_)*3 + region_label(wc*7 + jn);
        int rm = region_label(wr*7 + im )*3 + region_label(wc*7 + jm);
        if (rn != rm) acc -= 100.f;
        Ss[n][m] = acc;
    }
    __syncthreads();

    if (tid < NTOK) {
        float mx = -1e30f;
        #pragma unroll
        for (int m = 0; m < NTOK; m++) mx = fmaxf(mx, Ss[tid][m]);
        float s = 0.f;
        #pragma unroll
        for (int m = 0; m < NTOK; m++) { float e = __expf(Ss[tid][m] - mx); Ss[tid][m] = e; s += e; }
        float inv = 1.f / s;
        #pragma unroll
        for (int m = 0; m < NTOK; m++) Ss[tid][m] *= inv;
    }
    __syncthreads();

    float* out = g_att + (size_t)win*NTOK*DIM + h*HD;
    for (int e = tid; e < NTOK*HD; e += 128) {
        int n = e >> 5, d = e & 31;
        float acc = 0.f;
        #pragma unroll
        for (int m = 0; m < NTOK; m++) acc = fmaf(Ss[n][m], Vs[m][d], acc);
        out[(size_t)n*DIM + d] = acc;
    }
}

// ---------------- window reverse + unshift + residual add ----------------
// x1 = x + gather(proj_out_windows); one thread per float4
__global__ __launch_bounds__(256) void resid_scatter_kernel(const float* __restrict__ x)
{
    int idx = blockIdx.x*blockDim.x + threadIdx.x;
    if (idx >= MT*(DIM/4)) return;
    int t = idx >> 6, q = idx & 63;
    int bi = t / (HH*WW), l = t - bi*(HH*WW);
    int hh = l / WW, ww = l - hh*WW;
    int hs = hh + (HP - SSZ); if (hs >= HP) hs -= HP;
    int ws = ww + (HP - SSZ); if (ws >= HP) ws -= HP;
    int r = hs/7, i = hs - r*7, c = ws/7, j = ws - c*7;
    size_t m = ((size_t)bi*NWIN + r*9 + c)*NTOK + i*7 + j;
    float4 a = ((const float4*)x)[idx];
    float4 p = ((const float4*)g_xw)[m*(DIM/4) + q];   // proj output reuses g_xw
    a.x += p.x; a.y += p.y; a.z += p.z; a.w += p.w;
    ((float4*)g_x1)[idx] = a;
}

// ---------------- host launcher ----------------
extern "C" void kernel_launch(void* const* d_in, const int* in_sizes, int n_in,
                              void* d_out, int out_size)
{
    (void)in_sizes; (void)n_in; (void)out_size;
    const float* x      = (const float*)d_in[0];
    const float* g1     = (const float*)d_in[1];
    const float* b1     = (const float*)d_in[2];
    const float* w_qkv  = (const float*)d_in[3];
    const float* b_qkv  = (const float*)d_in[4];
    const float* relt   = (const float*)d_in[5];
    const float* w_proj = (const float*)d_in[6];
    const float* b_proj = (const float*)d_in[7];
    const float* g2     = (const float*)d_in[8];
    const float* b2     = (const float*)d_in[9];
    const float* w_fc1  = (const float*)d_in[10];
    const float* b_fc1  = (const float*)d_in[11];
    const float* w_fc2  = (const float*)d_in[12];
    const float* b_fc2  = (const float*)d_in[13];
    float* out = (float*)d_out;

    float *p_xw, *p_qkv, *p_att, *p_x1, *p_y, *p_h;
    cudaGetSymbolAddress((void**)&p_xw,  g_xw);
    cudaGetSymbolAddress((void**)&p_qkv, g_qkv);
    cudaGetSymbolAddress((void**)&p_att, g_att);
    cudaGetSymbolAddress((void**)&p_x1,  g_x1);
    cudaGetSymbolAddress((void**)&p_y,   g_y);
    cudaGetSymbolAddress((void**)&p_h,   g_h);

    // 1) LN1 + pad + shift + window partition
    {
        int warps = MW;
        int blocks = (warps*32 + 255)/256;
        ln1_window_kernel<<<blocks, 256>>>(x, g1, b1);
    }
    // 2) QKV GEMM: [MW,256] @ [256,768]
    sgemm_k<EPI_BIAS><<<dim3(768/128, (MW+127)/128), 256>>>(p_xw, w_qkv, b_qkv, nullptr, p_qkv, MW, 768, 256);
    // 3) windowed attention
    attn_kernel<<<BATCH*NWIN*NHEAD, 128>>>(relt);
    // 4) proj GEMM: [MW,256] @ [256,256] -> reuse g_xw
    sgemm_k<EPI_BIAS><<<dim3(256/128, (MW+127)/128), 256>>>(p_att, w_proj, b_proj, nullptr, p_xw, MW, 256, 256);
    // 5) window reverse + unshift + residual
    resid_scatter_kernel<<<(MT*(DIM/4) + 255)/256, 256>>>(x);
    // 6) LN2
    ln2_kernel<<<(MT*32 + 255)/256, 256>>>(g2, b2);
    // 7) fc1 + GELU: [MT,256] @ [256,1024]
    sgemm_k<EPI_GELU><<<dim3(1024/128, MT/128), 256>>>(p_y, w_fc1, b_fc1, nullptr, p_h, MT, 1024, 256);
    // 8) fc2 + bias + residual -> d_out: [MT,1024] @ [1024,256]
    sgemm_k<EPI_RES><<<dim3(256/128, MT/128), 256>>>(p_h, w_fc2, b_fc2, p_x1, out, MT, 256, 1024);
}

// round 6
// speedup vs baseline: 2.1979x; 2.1979x over previous
#include <cuda_runtime.h>
#include <math.h>
#include <stdint.h>

// ---------------- static config ----------------
#define BATCH 24
#define HH 60
#define WW 60
#define HP 63
#define WSZ 7
#define SSZ 3
#define NWIN 81          // 9x9 windows
#define NTOK 49          // tokens per window
#define DIM 256
#define NHEAD 8
#define HD 32
#define MW (BATCH*NWIN*NTOK)   // 95256 window tokens
#define MT (BATCH*HH*WW)       // 86400 real tokens

// GEMM tiling (mma.sync m16n8k8 tf32)
#define BM 128
#define BN 128
#define BK 32
#define ASTRIDE 36                 // A smem row stride (floats): bank-conflict-free
#define BSTRIDE 136                // B smem row stride (floats): bank-conflict-free
#define STGF (BM*ASTRIDE + BK*BSTRIDE)   // floats per stage = 4608+4352 = 8960
#define GEMM_SMEM (2*STGF*4)             // 71680 bytes

// ---------------- scratch (static device globals) ----------------
__device__ float g_xw[(size_t)MW*DIM];        // LN1 windowed input; reused as proj output
__device__ float g_qkv[(size_t)MW*3*DIM];
__device__ float g_att[(size_t)MW*DIM];
__device__ float g_x1[(size_t)MT*DIM];
__device__ float g_y [(size_t)MT*DIM];
__device__ float g_h [(size_t)MT*4*DIM];

// ---------------- helpers ----------------
__device__ __forceinline__ uint32_t smem_u32(const void* p){
    return (uint32_t)__cvta_generic_to_shared((void*)p);
}
__device__ __forceinline__ uint32_t cvt_tf32(float f){
    uint32_t r; asm("cvt.rna.tf32.f32 %0, %1;" : "=r"(r) : "f"(f)); return r;
}
__device__ __forceinline__ void mma1688(float* c, const uint32_t* a, const uint32_t* b){
    asm volatile("mma.sync.aligned.m16n8k8.row.col.f32.tf32.tf32.f32 "
        "{%0,%1,%2,%3}, {%4,%5,%6,%7}, {%8,%9}, {%0,%1,%2,%3};"
        : "+f"(c[0]),"+f"(c[1]),"+f"(c[2]),"+f"(c[3])
        : "r"(a[0]),"r"(a[1]),"r"(a[2]),"r"(a[3]), "r"(b[0]),"r"(b[1]));
}
__device__ __forceinline__ void cp16(uint32_t saddr, const void* g, int sz){
    asm volatile("cp.async.cg.shared.global [%0], [%1], 16, %2;"
                 :: "r"(saddr), "l"(g), "r"(sz) : "memory");
}
__device__ __forceinline__ float warp_sum(float v){
    #pragma unroll
    for (int o = 16; o; o >>= 1) v += __shfl_xor_sync(0xffffffffu, v, o);
    return v;
}
__device__ __forceinline__ int region_label(int p){
    return p < (HP - WSZ) ? 0 : (p < (HP - SSZ) ? 1 : 2);
}

// ---------------- LN1 + pad + shift + window partition ----------------
__global__ __launch_bounds__(256) void ln1_window_kernel(
    const float* __restrict__ x, const float* __restrict__ g, const float* __restrict__ b)
{
    int warp = (blockIdx.x * blockDim.x + threadIdx.x) >> 5;
    int lane = threadIdx.x & 31;
    if (warp >= MW) return;
    int bi  = warp / (NWIN*NTOK);
    int rem = warp - bi*(NWIN*NTOK);
    int w = rem / NTOK, n = rem - w*NTOK;
    int r = w/9, c = w - r*9, i = n/7, j = n - i*7;
    int hs = r*7 + i + SSZ; if (hs >= HP) hs -= HP;
    int ws = c*7 + j + SSZ; if (ws >= HP) ws -= HP;

    float4* dst = (float4*)(g_xw + (size_t)warp*DIM);
    if (hs >= HH || ws >= WW) {
        float4 z = make_float4(0.f,0.f,0.f,0.f);
        dst[lane] = z; dst[lane+32] = z;
        return;
    }
    const float4* src = (const float4*)(x + ((size_t)bi*(HH*WW) + hs*WW + ws)*DIM);
    float4 v0 = src[lane], v1 = src[lane+32];
    float s  = v0.x+v0.y+v0.z+v0.w + v1.x+v1.y+v1.z+v1.w;
    float ss = v0.x*v0.x+v0.y*v0.y+v0.z*v0.z+v0.w*v0.w
             + v1.x*v1.x+v1.y*v1.y+v1.z*v1.z+v1.w*v1.w;
    s  = warp_sum(s);
    ss = warp_sum(ss);
    float mu   = s * (1.f/DIM);
    float var  = ss * (1.f/DIM) - mu*mu;
    float rstd = rsqrtf(var + 1e-5f);
    const float4* gv = (const float4*)g;
    const float4* bv = (const float4*)b;
    float4 g0 = gv[lane], g1 = gv[lane+32], b0 = bv[lane], b1 = bv[lane+32];
    float4 o0, o1;
    o0.x = (v0.x-mu)*rstd*g0.x + b0.x;  o0.y = (v0.y-mu)*rstd*g0.y + b0.y;
    o0.z = (v0.z-mu)*rstd*g0.z + b0.z;  o0.w = (v0.w-mu)*rstd*g0.w + b0.w;
    o1.x = (v1.x-mu)*rstd*g1.x + b1.x;  o1.y = (v1.y-mu)*rstd*g1.y + b1.y;
    o1.z = (v1.z-mu)*rstd*g1.z + b1.z;  o1.w = (v1.w-mu)*rstd*g1.w + b1.w;
    dst[lane] = o0; dst[lane+32] = o1;
}

// ---------------- LN2 ----------------
__global__ __launch_bounds__(256) void ln2_kernel(
    const float* __restrict__ g, const float* __restrict__ b)
{
    int warp = (blockIdx.x * blockDim.x + threadIdx.x) >> 5;
    int lane = threadIdx.x & 31;
    if (warp >= MT) return;
    const float4* src = (const float4*)(g_x1 + (size_t)warp*DIM);
    float4* dst = (float4*)(g_y + (size_t)warp*DIM);
    float4 v0 = src[lane], v1 = src[lane+32];
    float s  = v0.x+v0.y+v0.z+v0.w + v1.x+v1.y+v1.z+v1.w;
    float ss = v0.x*v0.x+v0.y*v0.y+v0.z*v0.z+v0.w*v0.w
             + v1.x*v1.x+v1.y*v1.y+v1.z*v1.z+v1.w*v1.w;
    s  = warp_sum(s);
    ss = warp_sum(ss);
    float mu   = s * (1.f/DIM);
    float var  = ss * (1.f/DIM) - mu*mu;
    float rstd = rsqrtf(var + 1e-5f);
    const float4* gv = (const float4*)g;
    const float4* bv = (const float4*)b;
    float4 g0 = gv[lane], g1 = gv[lane+32], b0 = bv[lane], b1 = bv[lane+32];
    float4 o0, o1;
    o0.x = (v0.x-mu)*rstd*g0.x + b0.x;  o0.y = (v0.y-mu)*rstd*g0.y + b0.y;
    o0.z = (v0.z-mu)*rstd*g0.z + b0.z;  o0.w = (v0.w-mu)*rstd*g0.w + b0.w;
    o1.x = (v1.x-mu)*rstd*g1.x + b1.x;  o1.y = (v1.y-mu)*rstd*g1.y + b1.y;
    o1.z = (v1.z-mu)*rstd*g1.z + b1.z;  o1.w = (v1.w-mu)*rstd*g1.w + b1.w;
    dst[lane] = o0; dst[lane+32] = o1;
}

// ---------------- tf32 mma.sync GEMM ----------------
// C[M,N] = A[M,K] @ B[K,N] (+bias) (EPI: 0=bias, 1=bias+gelu, 2=bias+res)
// B consumed in natural [K,N] row-major layout.
template<int EPI>
__global__ __launch_bounds__(256) void tc_gemm(
    const float* __restrict__ A, const float* __restrict__ B,
    const float* __restrict__ bias, const float* __restrict__ Res,
    float* __restrict__ C, int M, int N, int K)
{
    extern __shared__ float sm[];
    const int tid = threadIdx.x;
    const int m0 = blockIdx.y * BM, n0 = blockIdx.x * BN;
    const int lane = tid & 31, warp = tid >> 5;
    const int wm = (warp >> 1) * 32;     // 4 warps along M
    const int wn = (warp & 1) * 64;      // 2 warps along N
    const int g = lane >> 2, t = lane & 3;

    float acc[2][8][4];
    #pragma unroll
    for (int mi = 0; mi < 2; mi++)
        #pragma unroll
        for (int ni = 0; ni < 8; ni++)
            #pragma unroll
            for (int q = 0; q < 4; q++) acc[mi][ni][q] = 0.f;

    const uint32_t sbase = smem_u32(sm);

    auto issue = [&](int kc, int s){
        const int k0 = kc * BK;
        // A tile: 128 rows x 32 floats (8 float4 per row)
        #pragma unroll
        for (int i = 0; i < 4; i++){
            int f = tid + i*256;
            int row = f >> 3, q = f & 7;
            int gr = m0 + row;
            int cl = gr < M ? gr : (M - 1);
            const float* src = A + (size_t)cl*K + k0 + q*4;
            cp16(sbase + (uint32_t)((s*STGF + row*ASTRIDE + q*4)*4), src, gr < M ? 16 : 0);
        }
        // B tile: 32 rows x 128 floats (32 float4 per row)
        #pragma unroll
        for (int i = 0; i < 4; i++){
            int f = tid + i*256;
            int row = f >> 5, q = f & 31;
            const float* src = B + (size_t)(k0 + row)*N + n0 + q*4;
            cp16(sbase + (uint32_t)((s*STGF + BM*ASTRIDE + row*BSTRIDE + q*4)*4), src, 16);
        }
        asm volatile("cp.async.commit_group;" ::: "memory");
    };

    const int nch = K / BK;
    issue(0, 0);
    for (int kc = 0; kc < nch; kc++){
        const int s = kc & 1;
        if (kc + 1 < nch){
            issue(kc + 1, s ^ 1);
            asm volatile("cp.async.wait_group 1;" ::: "memory");
        } else {
            asm volatile("cp.async.wait_group 0;" ::: "memory");
        }
        __syncthreads();
        const float* sa = sm + s*STGF;
        const float* sb = sa + BM*ASTRIDE;
        #pragma unroll
        for (int kk = 0; kk < 4; kk++){
            const int kb = kk * 8;
            uint32_t af[2][4];
            #pragma unroll
            for (int mi = 0; mi < 2; mi++){
                const float* ap = sa + (wm + mi*16 + g)*ASTRIDE + kb + t;
                af[mi][0] = cvt_tf32(ap[0]);
                af[mi][1] = cvt_tf32(ap[8*ASTRIDE]);
                af[mi][2] = cvt_tf32(ap[4]);
                af[mi][3] = cvt_tf32(ap[8*ASTRIDE + 4]);
            }
            #pragma unroll
            for (int ni = 0; ni < 8; ni++){
                const float* bp = sb + (kb + t)*BSTRIDE + wn + ni*8 + g;
                uint32_t bf[2];
                bf[0] = cvt_tf32(bp[0]);
                bf[1] = cvt_tf32(bp[4*BSTRIDE]);
                mma1688(acc[0][ni], af[0], bf);
                mma1688(acc[1][ni], af[1], bf);
            }
        }
        __syncthreads();
    }

    // epilogue: direct stores (float2 per reg-pair), sector-aligned
    #pragma unroll
    for (int mi = 0; mi < 2; mi++){
        const int r0 = m0 + wm + mi*16 + g;
        #pragma unroll
        for (int half = 0; half < 2; half++){
            const int gr = r0 + half*8;
            if (gr < M){
                #pragma unroll
                for (int ni = 0; ni < 8; ni++){
                    const int col = n0 + wn + ni*8 + t*2;
                    float2 bb = *(const float2*)(bias + col);
                    float v0 = acc[mi][ni][half*2 + 0] + bb.x;
                    float v1 = acc[mi][ni][half*2 + 1] + bb.y;
                    if (EPI == 1){
                        v0 = 0.5f*v0*(1.f + erff(v0*0.70710678118654752f));
                        v1 = 0.5f*v1*(1.f + erff(v1*0.70710678118654752f));
                    }
                    if (EPI == 2){
                        float2 rr = *(const float2*)(Res + (size_t)gr*N + col);
                        v0 += rr.x; v1 += rr.y;
                    }
                    *(float2*)(C + (size_t)gr*N + col) = make_float2(v0, v1);
                }
            }
        }
    }
}

// ---------------- attention: one block per (window, head) ----------------
__global__ __launch_bounds__(128) void attn_kernel(const float* __restrict__ relt)
{
    __shared__ float Qs[NTOK][33];
    __shared__ float Ks[NTOK][33];
    __shared__ float Vs[NTOK][33];
    __shared__ float Ss[NTOK][50];

    const int tid = threadIdx.x;
    const int wh  = blockIdx.x;
    const int win = wh >> 3;
    const int h   = wh & 7;

    const float* base = g_qkv + (size_t)win*NTOK*(3*DIM) + h*HD;
    const float scale = 0.17677669529663687f;
    for (int e = tid; e < NTOK*HD; e += 128) {
        int n = e >> 5, d = e & 31;
        const float* row = base + (size_t)n*(3*DIM);
        Qs[n][d] = row[d] * scale;
        Ks[n][d] = row[DIM + d];
        Vs[n][d] = row[2*DIM + d];
    }
    __syncthreads();

    const int w  = win % NWIN;
    const int wr = w / 9, wc = w - (w/9)*9;

    for (int e = tid; e < NTOK*NTOK; e += 128) {
        int n = e / NTOK, m = e - n*NTOK;
        float acc = 0.f;
        #pragma unroll
        for (int d = 0; d < HD; d++) acc = fmaf(Qs[n][d], Ks[m][d], acc);
        int in_ = n/7, jn = n - in_*7, im = m/7, jm = m - im*7;
        int idx = (in_ - im + 6)*13 + (jn - jm + 6);
        acc += __ldg(&relt[idx*NHEAD + h]);
        int rn = region_label(wr*7 + in_)*3 + region_label(wc*7 + jn);
        int rm = region_label(wr*7 + im )*3 + region_label(wc*7 + jm);
        if (rn != rm) acc -= 100.f;
        Ss[n][m] = acc;
    }
    __syncthreads();

    if (tid < NTOK) {
        float mx = -1e30f;
        #pragma unroll
        for (int m = 0; m < NTOK; m++) mx = fmaxf(mx, Ss[tid][m]);
        float s = 0.f;
        #pragma unroll
        for (int m = 0; m < NTOK; m++) { float e = __expf(Ss[tid][m] - mx); Ss[tid][m] = e; s += e; }
        float inv = 1.f / s;
        #pragma unroll
        for (int m = 0; m < NTOK; m++) Ss[tid][m] *= inv;
    }
    __syncthreads();

    float* out = g_att + (size_t)win*NTOK*DIM + h*HD;
    for (int e = tid; e < NTOK*HD; e += 128) {
        int n = e >> 5, d = e & 31;
        float acc = 0.f;
        #pragma unroll
        for (int m = 0; m < NTOK; m++) acc = fmaf(Ss[n][m], Vs[m][d], acc);
        out[(size_t)n*DIM + d] = acc;
    }
}

// ---------------- window reverse + unshift + residual ----------------
__global__ __launch_bounds__(256) void resid_scatter_kernel(const float* __restrict__ x)
{
    int idx = blockIdx.x*blockDim.x + threadIdx.x;
    if (idx >= MT*(DIM/4)) return;
    int t = idx >> 6, q = idx & 63;
    int bi = t / (HH*WW), l = t - bi*(HH*WW);
    int hh = l / WW, ww = l - hh*WW;
    int hs = hh + (HP - SSZ); if (hs >= HP) hs -= HP;
    int ws = ww + (HP - SSZ); if (ws >= HP) ws -= HP;
    int r = hs/7, i = hs - r*7, c = ws/7, j = ws - c*7;
    size_t m = ((size_t)bi*NWIN + r*9 + c)*NTOK + i*7 + j;
    float4 a = ((const float4*)x)[idx];
    float4 p = ((const float4*)g_xw)[m*(DIM/4) + q];
    a.x += p.x; a.y += p.y; a.z += p.z; a.w += p.w;
    ((float4*)g_x1)[idx] = a;
}

// ---------------- host launcher ----------------
extern "C" void kernel_launch(void* const* d_in, const int* in_sizes, int n_in,
                              void* d_out, int out_size)
{
    (void)in_sizes; (void)n_in; (void)out_size;
    const float* x      = (const float*)d_in[0];
    const float* g1     = (const float*)d_in[1];
    const float* b1     = (const float*)d_in[2];
    const float* w_qkv  = (const float*)d_in[3];
    const float* b_qkv  = (const float*)d_in[4];
    const float* relt   = (const float*)d_in[5];
    const float* w_proj = (const float*)d_in[6];
    const float* b_proj = (const float*)d_in[7];
    const float* g2     = (const float*)d_in[8];
    const float* b2     = (const float*)d_in[9];
    const float* w_fc1  = (const float*)d_in[10];
    const float* b_fc1  = (const float*)d_in[11];
    const float* w_fc2  = (const float*)d_in[12];
    const float* b_fc2  = (const float*)d_in[13];
    float* out = (float*)d_out;

    float *p_xw, *p_qkv, *p_att, *p_x1, *p_y, *p_h;
    cudaGetSymbolAddress((void**)&p_xw,  g_xw);
    cudaGetSymbolAddress((void**)&p_qkv, g_qkv);
    cudaGetSymbolAddress((void**)&p_att, g_att);
    cudaGetSymbolAddress((void**)&p_x1,  g_x1);
    cudaGetSymbolAddress((void**)&p_y,   g_y);
    cudaGetSymbolAddress((void**)&p_h,   g_h);

    cudaFuncSetAttribute(tc_gemm<0>, cudaFuncAttributeMaxDynamicSharedMemorySize, GEMM_SMEM);
    cudaFuncSetAttribute(tc_gemm<1>, cudaFuncAttributeMaxDynamicSharedMemorySize, GEMM_SMEM);
    cudaFuncSetAttribute(tc_gemm<2>, cudaFuncAttributeMaxDynamicSharedMemorySize, GEMM_SMEM);

    // 1) LN1 + pad + shift + window partition
    ln1_window_kernel<<<(MW*32 + 255)/256, 256>>>(x, g1, b1);

    // 2) QKV GEMM [MW,256]x[256,768]
    tc_gemm<0><<<dim3(768/BN, (MW + BM - 1)/BM), 256, GEMM_SMEM>>>(
        p_xw, w_qkv, b_qkv, (const float*)0, p_qkv, MW, 768, 256);

    // 3) attention
    attn_kernel<<<BATCH*NWIN*NHEAD, 128>>>(relt);

    // 4) proj GEMM [MW,256]x[256,256] -> g_xw
    tc_gemm<0><<<dim3(256/BN, (MW + BM - 1)/BM), 256, GEMM_SMEM>>>(
        p_att, w_proj, b_proj, (const float*)0, p_xw, MW, 256, 256);

    // 5) window reverse + unshift + residual
    resid_scatter_kernel<<<(MT*(DIM/4) + 255)/256, 256>>>(x);

    // 6) LN2
    ln2_kernel<<<(MT*32 + 255)/256, 256>>>(g2, b2);

    // 7) fc1 + GELU [MT,256]x[256,1024]
    tc_gemm<1><<<dim3(1024/BN, MT/BM), 256, GEMM_SMEM>>>(
        p_y, w_fc1, b_fc1, (const float*)0, p_h, MT, 1024, 256);

    // 8) fc2 + bias + residual -> out [MT,1024]x[1024,256]
    tc_gemm<2><<<dim3(256/BN, MT/BM), 256, GEMM_SMEM>>>(
        p_h, w_fc2, b_fc2, p_x1, out, MT, 256, 1024);
}

// round 7
// speedup vs baseline: 2.5702x; 1.1694x over previous
#include <cuda_runtime.h>
#include <math.h>
#include <stdint.h>

// ---------------- static config ----------------
#define BATCH 24
#define HH 60
#define WW 60
#define HP 63
#define WSZ 7
#define SSZ 3
#define NWIN 81          // 9x9 windows
#define NTOK 49          // tokens per window
#define DIM 256
#define NHEAD 8
#define HD 32
#define MW (BATCH*NWIN*NTOK)   // 95256 window tokens
#define MT (BATCH*HH*WW)       // 86400 real tokens

// GEMM tiling (mma.sync m16n8k8 tf32)
#define BM 128
#define BN 128
#define BK 32
#define ASTRIDE 36                 // A smem row stride (floats): bank-conflict-free
#define BSTRIDE 136                // B smem row stride (floats): bank-conflict-free
#define STGF (BM*ASTRIDE + BK*BSTRIDE)   // floats per stage = 4608+4352 = 8960
#define GEMM_SMEM (2*STGF*4)             // 71680 bytes

// ---------------- scratch (static device globals) ----------------
__device__ float g_xw[(size_t)MW*DIM];        // LN1 windowed input; reused as proj output
__device__ float g_qkv[(size_t)MW*3*DIM];
__device__ float g_att[(size_t)MW*DIM];
__device__ float g_x1[(size_t)MT*DIM];
__device__ float g_y [(size_t)MT*DIM];
__device__ float g_h [(size_t)MT*4*DIM];

// ---------------- helpers ----------------
__device__ __forceinline__ uint32_t smem_u32(const void* p){
    return (uint32_t)__cvta_generic_to_shared((void*)p);
}
__device__ __forceinline__ void mma1688(float* c, const uint32_t* a, const uint32_t* b){
    asm volatile("mma.sync.aligned.m16n8k8.row.col.f32.tf32.tf32.f32 "
        "{%0,%1,%2,%3}, {%4,%5,%6,%7}, {%8,%9}, {%0,%1,%2,%3};"
        : "+f"(c[0]),"+f"(c[1]),"+f"(c[2]),"+f"(c[3])
        : "r"(a[0]),"r"(a[1]),"r"(a[2]),"r"(a[3]), "r"(b[0]),"r"(b[1]));
}
__device__ __forceinline__ void cp16(uint32_t saddr, const void* g, int sz){
    asm volatile("cp.async.cg.shared.global [%0], [%1], 16, %2;"
                 :: "r"(saddr), "l"(g), "r"(sz) : "memory");
}
__device__ __forceinline__ float warp_sum(float v){
    #pragma unroll
    for (int o = 16; o; o >>= 1) v += __shfl_xor_sync(0xffffffffu, v, o);
    return v;
}
__device__ __forceinline__ int region_label(int p){
    return p < (HP - WSZ) ? 0 : (p < (HP - SSZ) ? 1 : 2);
}

// ---------------- LN1 + pad + shift + window partition ----------------
__global__ __launch_bounds__(256) void ln1_window_kernel(
    const float* __restrict__ x, const float* __restrict__ g, const float* __restrict__ b)
{
    int warp = (blockIdx.x * blockDim.x + threadIdx.x) >> 5;
    int lane = threadIdx.x & 31;
    if (warp >= MW) return;
    int bi  = warp / (NWIN*NTOK);
    int rem = warp - bi*(NWIN*NTOK);
    int w = rem / NTOK, n = rem - w*NTOK;
    int r = w/9, c = w - r*9, i = n/7, j = n - i*7;
    int hs = r*7 + i + SSZ; if (hs >= HP) hs -= HP;
    int ws = c*7 + j + SSZ; if (ws >= HP) ws -= HP;

    float4* dst = (float4*)(g_xw + (size_t)warp*DIM);
    if (hs >= HH || ws >= WW) {
        float4 z = make_float4(0.f,0.f,0.f,0.f);
        dst[lane] = z; dst[lane+32] = z;
        return;
    }
    const float4* src = (const float4*)(x + ((size_t)bi*(HH*WW) + hs*WW + ws)*DIM);
    float4 v0 = src[lane], v1 = src[lane+32];
    float s  = v0.x+v0.y+v0.z+v0.w + v1.x+v1.y+v1.z+v1.w;
    float ss = v0.x*v0.x+v0.y*v0.y+v0.z*v0.z+v0.w*v0.w
             + v1.x*v1.x+v1.y*v1.y+v1.z*v1.z+v1.w*v1.w;
    s  = warp_sum(s);
    ss = warp_sum(ss);
    float mu   = s * (1.f/DIM);
    float var  = ss * (1.f/DIM) - mu*mu;
    float rstd = rsqrtf(var + 1e-5f);
    const float4* gv = (const float4*)g;
    const float4* bv = (const float4*)b;
    float4 g0 = gv[lane], g1 = gv[lane+32], b0 = bv[lane], b1 = bv[lane+32];
    float4 o0, o1;
    o0.x = (v0.x-mu)*rstd*g0.x + b0.x;  o0.y = (v0.y-mu)*rstd*g0.y + b0.y;
    o0.z = (v0.z-mu)*rstd*g0.z + b0.z;  o0.w = (v0.w-mu)*rstd*g0.w + b0.w;
    o1.x = (v1.x-mu)*rstd*g1.x + b1.x;  o1.y = (v1.y-mu)*rstd*g1.y + b1.y;
    o1.z = (v1.z-mu)*rstd*g1.z + b1.z;  o1.w = (v1.w-mu)*rstd*g1.w + b1.w;
    dst[lane] = o0; dst[lane+32] = o1;
}

// ---------------- LN2 ----------------
__global__ __launch_bounds__(256) void ln2_kernel(
    const float* __restrict__ g, const float* __restrict__ b)
{
    int warp = (blockIdx.x * blockDim.x + threadIdx.x) >> 5;
    int lane = threadIdx.x & 31;
    if (warp >= MT) return;
    const float4* src = (const float4*)(g_x1 + (size_t)warp*DIM);
    float4* dst = (float4*)(g_y + (size_t)warp*DIM);
    float4 v0 = src[lane], v1 = src[lane+32];
    float s  = v0.x+v0.y+v0.z+v0.w + v1.x+v1.y+v1.z+v1.w;
    float ss = v0.x*v0.x+v0.y*v0.y+v0.z*v0.z+v0.w*v0.w
             + v1.x*v1.x+v1.y*v1.y+v1.z*v1.z+v1.w*v1.w;
    s  = warp_sum(s);
    ss = warp_sum(ss);
    float mu   = s * (1.f/DIM);
    float var  = ss * (1.f/DIM) - mu*mu;
    float rstd = rsqrtf(var + 1e-5f);
    const float4* gv = (const float4*)g;
    const float4* bv = (const float4*)b;
    float4 g0 = gv[lane], g1 = gv[lane+32], b0 = bv[lane], b1 = bv[lane+32];
    float4 o0, o1;
    o0.x = (v0.x-mu)*rstd*g0.x + b0.x;  o0.y = (v0.y-mu)*rstd*g0.y + b0.y;
    o0.z = (v0.z-mu)*rstd*g0.z + b0.z;  o0.w = (v0.w-mu)*rstd*g0.w + b0.w;
    o1.x = (v1.x-mu)*rstd*g1.x + b1.x;  o1.y = (v1.y-mu)*rstd*g1.y + b1.y;
    o1.z = (v1.z-mu)*rstd*g1.z + b1.z;  o1.w = (v1.w-mu)*rstd*g1.w + b1.w;
    dst[lane] = o0; dst[lane+32] = o1;
}

// ---------------- tf32 mma.sync GEMM ----------------
// C[M,N] = A[M,K] @ B[K,N] (+bias) (EPI: 0=bias, 1=bias+gelu, 2=bias+res)
// B consumed in natural [K,N] row-major layout.
// Fragments are fed as RAW fp32 bits (HW truncates to tf32) — no cvt in hot loop.
template<int EPI>
__global__ __launch_bounds__(256, 2) void tc_gemm(
    const float* __restrict__ A, const float* __restrict__ B,
    const float* __restrict__ bias, const float* __restrict__ Res,
    float* __restrict__ C, int M, int N, int K)
{
    extern __shared__ float sm[];
    const int tid = threadIdx.x;
    const int m0 = blockIdx.y * BM, n0 = blockIdx.x * BN;
    const int lane = tid & 31, warp = tid >> 5;
    const int wm = (warp >> 1) * 32;     // 4 warps along M
    const int wn = (warp & 1) * 64;      // 2 warps along N
    const int g = lane >> 2, t = lane & 3;

    float acc[2][8][4];
    #pragma unroll
    for (int mi = 0; mi < 2; mi++)
        #pragma unroll
        for (int ni = 0; ni < 8; ni++)
            #pragma unroll
            for (int q = 0; q < 4; q++) acc[mi][ni][q] = 0.f;

    const uint32_t sbase = smem_u32(sm);

    auto issue = [&](int kc, int s){
        const int k0 = kc * BK;
        // A tile: 128 rows x 32 floats (8 float4 per row)
        #pragma unroll
        for (int i = 0; i < 4; i++){
            int f = tid + i*256;
            int row = f >> 3, q = f & 7;
            int gr = m0 + row;
            int cl = gr < M ? gr : (M - 1);
            const float* src = A + (size_t)cl*K + k0 + q*4;
            cp16(sbase + (uint32_t)((s*STGF + row*ASTRIDE + q*4)*4), src, gr < M ? 16 : 0);
        }
        // B tile: 32 rows x 128 floats (32 float4 per row)
        #pragma unroll
        for (int i = 0; i < 4; i++){
            int f = tid + i*256;
            int row = f >> 5, q = f & 31;
            const float* src = B + (size_t)(k0 + row)*N + n0 + q*4;
            cp16(sbase + (uint32_t)((s*STGF + BM*ASTRIDE + row*BSTRIDE + q*4)*4), src, 16);
        }
        asm volatile("cp.async.commit_group;" ::: "memory");
    };

    const int nch = K / BK;
    issue(0, 0);
    for (int kc = 0; kc < nch; kc++){
        const int s = kc & 1;
        if (kc + 1 < nch){
            issue(kc + 1, s ^ 1);
            asm volatile("cp.async.wait_group 1;" ::: "memory");
        } else {
            asm volatile("cp.async.wait_group 0;" ::: "memory");
        }
        __syncthreads();
        const uint32_t* sa = (const uint32_t*)(sm + s*STGF);
        const uint32_t* sb = sa + BM*ASTRIDE;
        #pragma unroll
        for (int kk = 0; kk < 4; kk++){
            const int kb = kk * 8;
            uint32_t af[2][4];
            #pragma unroll
            for (int mi = 0; mi < 2; mi++){
                const uint32_t* ap = sa + (wm + mi*16 + g)*ASTRIDE + kb + t;
                af[mi][0] = ap[0];
                af[mi][1] = ap[8*ASTRIDE];
                af[mi][2] = ap[4];
                af[mi][3] = ap[8*ASTRIDE + 4];
            }
            #pragma unroll
            for (int ni = 0; ni < 8; ni++){
                const uint32_t* bp = sb + (kb + t)*BSTRIDE + wn + ni*8 + g;
                uint32_t bf[2];
                bf[0] = bp[0];
                bf[1] = bp[4*BSTRIDE];
                mma1688(acc[0][ni], af[0], bf);
                mma1688(acc[1][ni], af[1], bf);
            }
        }
        __syncthreads();
    }

    // epilogue: direct stores (float2 per reg-pair), sector-aligned
    #pragma unroll
    for (int mi = 0; mi < 2; mi++){
        const int r0 = m0 + wm + mi*16 + g;
        #pragma unroll
        for (int half = 0; half < 2; half++){
            const int gr = r0 + half*8;
            if (gr < M){
                #pragma unroll
                for (int ni = 0; ni < 8; ni++){
                    const int col = n0 + wn + ni*8 + t*2;
                    float2 bb = *(const float2*)(bias + col);
                    float v0 = acc[mi][ni][half*2 + 0] + bb.x;
                    float v1 = acc[mi][ni][half*2 + 1] + bb.y;
                    if (EPI == 1){
                        v0 = 0.5f*v0*(1.f + erff(v0*0.70710678118654752f));
                        v1 = 0.5f*v1*(1.f + erff(v1*0.70710678118654752f));
                    }
                    if (EPI == 2){
                        float2 rr = *(const float2*)(Res + (size_t)gr*N + col);
                        v0 += rr.x; v1 += rr.y;
                    }
                    *(float2*)(C + (size_t)gr*N + col) = make_float2(v0, v1);
                }
            }
        }
    }
}

// ---------------- attention: one block per (window, head) ----------------
__global__ __launch_bounds__(128) void attn_kernel(const float* __restrict__ relt)
{
    __shared__ float Qs[NTOK][33];
    __shared__ float Ks[NTOK][33];
    __shared__ float Vs[NTOK][33];
    __shared__ float Ss[NTOK][50];

    const int tid = threadIdx.x;
    const int wh  = blockIdx.x;
    const int win = wh >> 3;
    const int h   = wh & 7;

    const float* base = g_qkv + (size_t)win*NTOK*(3*DIM) + h*HD;
    const float scale = 0.17677669529663687f;
    for (int e = tid; e < NTOK*HD; e += 128) {
        int n = e >> 5, d = e & 31;
        const float* row = base + (size_t)n*(3*DIM);
        Qs[n][d] = row[d] * scale;
        Ks[n][d] = row[DIM + d];
        Vs[n][d] = row[2*DIM + d];
    }
    __syncthreads();

    const int w  = win % NWIN;
    const int wr = w / 9, wc = w - (w/9)*9;

    for (int e = tid; e < NTOK*NTOK; e += 128) {
        int n = e / NTOK, m = e - n*NTOK;
        float acc = 0.f;
        #pragma unroll
        for (int d = 0; d < HD; d++) acc = fmaf(Qs[n][d], Ks[m][d], acc);
        int in_ = n/7, jn = n - in_*7, im = m/7, jm = m - im*7;
        int idx = (in_ - im + 6)*13 + (jn - jm + 6);
        acc += __ldg(&relt[idx*NHEAD + h]);
        int rn = region_label(wr*7 + in_)*3 + region_label(wc*7 + jn);
        int rm = region_label(wr*7 + im )*3 + region_label(wc*7 + jm);
        if (rn != rm) acc -= 100.f;
        Ss[n][m] = acc;
    }
    __syncthreads();

    if (tid < NTOK) {
        float mx = -1e30f;
        #pragma unroll
        for (int m = 0; m < NTOK; m++) mx = fmaxf(mx, Ss[tid][m]);
        float s = 0.f;
        #pragma unroll
        for (int m = 0; m < NTOK; m++) { float e = __expf(Ss[tid][m] - mx); Ss[tid][m] = e; s += e; }
        float inv = 1.f / s;
        #pragma unroll
        for (int m = 0; m < NTOK; m++) Ss[tid][m] *= inv;
    }
    __syncthreads();

    float* out = g_att + (size_t)win*NTOK*DIM + h*HD;
    for (int e = tid; e < NTOK*HD; e += 128) {
        int n = e >> 5, d = e & 31;
        float acc = 0.f;
        #pragma unroll
        for (int m = 0; m < NTOK; m++) acc = fmaf(Ss[n][m], Vs[m][d], acc);
        out[(size_t)n*DIM + d] = acc;
    }
}

// ---------------- window reverse + unshift + residual ----------------
__global__ __launch_bounds__(256) void resid_scatter_kernel(const float* __restrict__ x)
{
    int idx = blockIdx.x*blockDim.x + threadIdx.x;
    if (idx >= MT*(DIM/4)) return;
    int t = idx >> 6, q = idx & 63;
    int bi = t / (HH*WW), l = t - bi*(HH*WW);
    int hh = l / WW, ww = l - hh*WW;
    int hs = hh + (HP - SSZ); if (hs >= HP) hs -= HP;
    int ws = ww + (HP - SSZ); if (ws >= HP) ws -= HP;
    int r = hs/7, i = hs - r*7, c = ws/7, j = ws - c*7;
    size_t m = ((size_t)bi*NWIN + r*9 + c)*NTOK + i*7 + j;
    float4 a = ((const float4*)x)[idx];
    float4 p = ((const float4*)g_xw)[m*(DIM/4) + q];
    a.x += p.x; a.y += p.y; a.z += p.z; a.w += p.w;
    ((float4*)g_x1)[idx] = a;
}

// ---------------- host launcher ----------------
extern "C" void kernel_launch(void* const* d_in, const int* in_sizes, int n_in,
                              void* d_out, int out_size)
{
    (void)in_sizes; (void)n_in; (void)out_size;
    const float* x      = (const float*)d_in[0];
    const float* g1     = (const float*)d_in[1];
    const float* b1     = (const float*)d_in[2];
    const float* w_qkv  = (const float*)d_in[3];
    const float* b_qkv  = (const float*)d_in[4];
    const float* relt   = (const float*)d_in[5];
    const float* w_proj = (const float*)d_in[6];
    const float* b_proj = (const float*)d_in[7];
    const float* g2     = (const float*)d_in[8];
    const float* b2     = (const float*)d_in[9];
    const float* w_fc1  = (const float*)d_in[10];
    const float* b_fc1  = (const float*)d_in[11];
    const float* w_fc2  = (const float*)d_in[12];
    const float* b_fc2  = (const float*)d_in[13];
    float* out = (float*)d_out;

    float *p_xw, *p_qkv, *p_att, *p_x1, *p_y, *p_h;
    cudaGetSymbolAddress((void**)&p_xw,  g_xw);
    cudaGetSymbolAddress((void**)&p_qkv, g_qkv);
    cudaGetSymbolAddress((void**)&p_att, g_att);
    cudaGetSymbolAddress((void**)&p_x1,  g_x1);
    cudaGetSymbolAddress((void**)&p_y,   g_y);
    cudaGetSymbolAddress((void**)&p_h,   g_h);

    cudaFuncSetAttribute(tc_gemm<0>, cudaFuncAttributeMaxDynamicSharedMemorySize, GEMM_SMEM);
    cudaFuncSetAttribute(tc_gemm<1>, cudaFuncAttributeMaxDynamicSharedMemorySize, GEMM_SMEM);
    cudaFuncSetAttribute(tc_gemm<2>, cudaFuncAttributeMaxDynamicSharedMemorySize, GEMM_SMEM);

    // 1) LN1 + pad + shift + window partition
    ln1_window_kernel<<<(MW*32 + 255)/256, 256>>>(x, g1, b1);

    // 2) QKV GEMM [MW,256]x[256,768]
    tc_gemm<0><<<dim3(768/BN, (MW + BM - 1)/BM), 256, GEMM_SMEM>>>(
        p_xw, w_qkv, b_qkv, (const float*)0, p_qkv, MW, 768, 256);

    // 3) attention
    attn_kernel<<<BATCH*NWIN*NHEAD, 128>>>(relt);

    // 4) proj GEMM [MW,256]x[256,256] -> g_xw
    tc_gemm<0><<<dim3(256/BN, (MW + BM - 1)/BM), 256, GEMM_SMEM>>>(
        p_att, w_proj, b_proj, (const float*)0, p_xw, MW, 256, 256);

    // 5) window reverse + unshift + residual
    resid_scatter_kernel<<<(MT*(DIM/4) + 255)/256, 256>>>(x);

    // 6) LN2
    ln2_kernel<<<(MT*32 + 255)/256, 256>>>(g2, b2);

    // 7) fc1 + GELU [MT,256]x[256,1024]
    tc_gemm<1><<<dim3(1024/BN, MT/BM), 256, GEMM_SMEM>>>(
        p_y, w_fc1, b_fc1, (const float*)0, p_h, MT, 1024, 256);

    // 8) fc2 + bias + residual -> out [MT,1024]x[1024,256]
    tc_gemm<2><<<dim3(256/BN, MT/BM), 256, GEMM_SMEM>>>(
        p_h, w_fc2, b_fc2, p_x1, out, MT, 256, 1024);
}

// round 8
// speedup vs baseline: 3.1203x; 1.2140x over previous
#include <cuda_runtime.h>
#include <math.h>
#include <stdint.h>

// ---------------- static config ----------------
#define BATCH 24
#define HH 60
#define WW 60
#define HP 63
#define WSZ 7
#define SSZ 3
#define NWIN 81          // 9x9 windows
#define NTOK 49          // tokens per window
#define DIM 256
#define NHEAD 8
#define HD 32
#define MW (BATCH*NWIN*NTOK)   // 95256 window tokens
#define MT (BATCH*HH*WW)       // 86400 real tokens

// GEMM tiling (mma.sync m16n8k8 tf32)
#define BM 128
#define BN 128
#define BK 32
#define ASTRIDE 36                 // A smem row stride (floats): bank-conflict-free
#define BSTRIDE 136                // B smem row stride (floats): bank-conflict-free
#define STGF (BM*ASTRIDE + BK*BSTRIDE)   // floats per stage = 4608+4352 = 8960
#define NSTAGE 3
#define GEMM_SMEM (NSTAGE*STGF*4)        // 107520 bytes

// ---------------- scratch (static device globals) ----------------
__device__ float g_xw[(size_t)MW*DIM];        // LN1 windowed input; reused as proj output
__device__ float g_qkv[(size_t)MW*3*DIM];
__device__ float g_att[(size_t)MW*DIM];
__device__ float g_x1[(size_t)MT*DIM];
__device__ float g_y [(size_t)MT*DIM];
__device__ float g_h [(size_t)MT*4*DIM];

// ---------------- helpers ----------------
__device__ __forceinline__ uint32_t smem_u32(const void* p){
    return (uint32_t)__cvta_generic_to_shared((void*)p);
}
__device__ __forceinline__ void mma1688(float* c, const uint32_t* a, const uint32_t* b){
    asm volatile("mma.sync.aligned.m16n8k8.row.col.f32.tf32.tf32.f32 "
        "{%0,%1,%2,%3}, {%4,%5,%6,%7}, {%8,%9}, {%0,%1,%2,%3};"
        : "+f"(c[0]),"+f"(c[1]),"+f"(c[2]),"+f"(c[3])
        : "r"(a[0]),"r"(a[1]),"r"(a[2]),"r"(a[3]), "r"(b[0]),"r"(b[1]));
}
__device__ __forceinline__ void cp16(uint32_t saddr, const void* g, int sz){
    asm volatile("cp.async.cg.shared.global [%0], [%1], 16, %2;"
                 :: "r"(saddr), "l"(g), "r"(sz) : "memory");
}
__device__ __forceinline__ float warp_sum(float v){
    #pragma unroll
    for (int o = 16; o; o >>= 1) v += __shfl_xor_sync(0xffffffffu, v, o);
    return v;
}
__device__ __forceinline__ int region_label(int p){
    return p < (HP - WSZ) ? 0 : (p < (HP - SSZ) ? 1 : 2);
}

// ---------------- LN1 + pad + shift + window partition ----------------
__global__ __launch_bounds__(256) void ln1_window_kernel(
    const float* __restrict__ x, const float* __restrict__ g, const float* __restrict__ b)
{
    int warp = (blockIdx.x * blockDim.x + threadIdx.x) >> 5;
    int lane = threadIdx.x & 31;
    if (warp >= MW) return;
    int bi  = warp / (NWIN*NTOK);
    int rem = warp - bi*(NWIN*NTOK);
    int w = rem / NTOK, n = rem - w*NTOK;
    int r = w/9, c = w - r*9, i = n/7, j = n - i*7;
    int hs = r*7 + i + SSZ; if (hs >= HP) hs -= HP;
    int ws = c*7 + j + SSZ; if (ws >= HP) ws -= HP;

    float4* dst = (float4*)(g_xw + (size_t)warp*DIM);
    if (hs >= HH || ws >= WW) {
        float4 z = make_float4(0.f,0.f,0.f,0.f);
        dst[lane] = z; dst[lane+32] = z;
        return;
    }
    const float4* src = (const float4*)(x + ((size_t)bi*(HH*WW) + hs*WW + ws)*DIM);
    float4 v0 = src[lane], v1 = src[lane+32];
    float s  = v0.x+v0.y+v0.z+v0.w + v1.x+v1.y+v1.z+v1.w;
    float ss = v0.x*v0.x+v0.y*v0.y+v0.z*v0.z+v0.w*v0.w
             + v1.x*v1.x+v1.y*v1.y+v1.z*v1.z+v1.w*v1.w;
    s  = warp_sum(s);
    ss = warp_sum(ss);
    float mu   = s * (1.f/DIM);
    float var  = ss * (1.f/DIM) - mu*mu;
    float rstd = rsqrtf(var + 1e-5f);
    const float4* gv = (const float4*)g;
    const float4* bv = (const float4*)b;
    float4 g0 = gv[lane], g1 = gv[lane+32], b0 = bv[lane], b1 = bv[lane+32];
    float4 o0, o1;
    o0.x = (v0.x-mu)*rstd*g0.x + b0.x;  o0.y = (v0.y-mu)*rstd*g0.y + b0.y;
    o0.z = (v0.z-mu)*rstd*g0.z + b0.z;  o0.w = (v0.w-mu)*rstd*g0.w + b0.w;
    o1.x = (v1.x-mu)*rstd*g1.x + b1.x;  o1.y = (v1.y-mu)*rstd*g1.y + b1.y;
    o1.z = (v1.z-mu)*rstd*g1.z + b1.z;  o1.w = (v1.w-mu)*rstd*g1.w + b1.w;
    dst[lane] = o0; dst[lane+32] = o1;
}

// ---------------- window reverse + unshift + residual + LN2 (fused) ----------------
// one warp per real token: x1 = x + gather(proj_windows); g_x1 = x1; g_y = LN(x1)
__global__ __launch_bounds__(256) void resid_ln2_kernel(
    const float* __restrict__ x, const float* __restrict__ g, const float* __restrict__ b)
{
    int warp = (blockIdx.x * blockDim.x + threadIdx.x) >> 5;
    int lane = threadIdx.x & 31;
    if (warp >= MT) return;
    int bi = warp / (HH*WW), l = warp - bi*(HH*WW);
    int hh = l / WW, ww = l - hh*WW;
    int hs = hh + (HP - SSZ); if (hs >= HP) hs -= HP;
    int ws = ww + (HP - SSZ); if (ws >= HP) ws -= HP;
    int r = hs/7, i = hs - r*7, c = ws/7, j = ws - c*7;
    size_t m = ((size_t)bi*NWIN + r*9 + c)*NTOK + i*7 + j;

    const float4* xs = (const float4*)(x + (size_t)warp*DIM);
    const float4* ps = (const float4*)(g_xw + m*DIM);
    float4 a0 = xs[lane], a1 = xs[lane+32];
    float4 p0 = ps[lane], p1 = ps[lane+32];
    a0.x += p0.x; a0.y += p0.y; a0.z += p0.z; a0.w += p0.w;
    a1.x += p1.x; a1.y += p1.y; a1.z += p1.z; a1.w += p1.w;
    float4* x1 = (float4*)(g_x1 + (size_t)warp*DIM);
    x1[lane] = a0; x1[lane+32] = a1;

    float s  = a0.x+a0.y+a0.z+a0.w + a1.x+a1.y+a1.z+a1.w;
    float ss = a0.x*a0.x+a0.y*a0.y+a0.z*a0.z+a0.w*a0.w
             + a1.x*a1.x+a1.y*a1.y+a1.z*a1.z+a1.w*a1.w;
    s  = warp_sum(s);
    ss = warp_sum(ss);
    float mu   = s * (1.f/DIM);
    float var  = ss * (1.f/DIM) - mu*mu;
    float rstd = rsqrtf(var + 1e-5f);
    const float4* gv = (const float4*)g;
    const float4* bv = (const float4*)b;
    float4 g0 = gv[lane], g1 = gv[lane+32], b0 = bv[lane], b1 = bv[lane+32];
    float4 o0, o1;
    o0.x = (a0.x-mu)*rstd*g0.x + b0.x;  o0.y = (a0.y-mu)*rstd*g0.y + b0.y;
    o0.z = (a0.z-mu)*rstd*g0.z + b0.z;  o0.w = (a0.w-mu)*rstd*g0.w + b0.w;
    o1.x = (a1.x-mu)*rstd*g1.x + b1.x;  o1.y = (a1.y-mu)*rstd*g1.y + b1.y;
    o1.z = (a1.z-mu)*rstd*g1.z + b1.z;  o1.w = (a1.w-mu)*rstd*g1.w + b1.w;
    float4* dst = (float4*)(g_y + (size_t)warp*DIM);
    dst[lane] = o0; dst[lane+32] = o1;
}

// ---------------- tf32 mma.sync GEMM, 3-stage cp.async pipeline ----------------
// C[M,N] = A[M,K] @ B[K,N] (+bias) (EPI: 0=bias, 1=bias+gelu, 2=bias+res)
template<int EPI>
__global__ __launch_bounds__(256, 2) void tc_gemm(
    const float* __restrict__ A, const float* __restrict__ B,
    const float* __restrict__ bias, const float* __restrict__ Res,
    float* __restrict__ C, int M, int N, int K)
{
    extern __shared__ float sm[];
    const int tid = threadIdx.x;
    const int m0 = blockIdx.y * BM, n0 = blockIdx.x * BN;
    const int lane = tid & 31, warp = tid >> 5;
    const int wm = (warp >> 1) * 32;     // 4 warps along M
    const int wn = (warp & 1) * 64;      // 2 warps along N
    const int g = lane >> 2, t = lane & 3;

    float acc[2][8][4];
    #pragma unroll
    for (int mi = 0; mi < 2; mi++)
        #pragma unroll
        for (int ni = 0; ni < 8; ni++)
            #pragma unroll
            for (int q = 0; q < 4; q++) acc[mi][ni][q] = 0.f;

    const uint32_t sbase = smem_u32(sm);

    auto issue = [&](int kc, int s){
        const int k0 = kc * BK;
        #pragma unroll
        for (int i = 0; i < 4; i++){
            int f = tid + i*256;
            int row = f >> 3, q = f & 7;
            int gr = m0 + row;
            int cl = gr < M ? gr : (M - 1);
            const float* src = A + (size_t)cl*K + k0 + q*4;
            cp16(sbase + (uint32_t)((s*STGF + row*ASTRIDE + q*4)*4), src, gr < M ? 16 : 0);
        }
        #pragma unroll
        for (int i = 0; i < 4; i++){
            int f = tid + i*256;
            int row = f >> 5, q = f & 31;
            const float* src = B + (size_t)(k0 + row)*N + n0 + q*4;
            cp16(sbase + (uint32_t)((s*STGF + BM*ASTRIDE + row*BSTRIDE + q*4)*4), src, 16);
        }
        asm volatile("cp.async.commit_group;" ::: "memory");
    };

    const int nch = K / BK;
    issue(0, 0);
    if (nch > 1) issue(1, 1);
    int s = 0;
    for (int kc = 0; kc < nch; kc++){
        if (kc + 1 < nch){
            asm volatile("cp.async.wait_group 1;" ::: "memory");
        } else {
            asm volatile("cp.async.wait_group 0;" ::: "memory");
        }
        __syncthreads();
        if (kc + 2 < nch){
            int s2 = s + 2; if (s2 >= NSTAGE) s2 -= NSTAGE;
            issue(kc + 2, s2);
        }
        const uint32_t* sa = (const uint32_t*)(sm + s*STGF);
        const uint32_t* sb = sa + BM*ASTRIDE;
        #pragma unroll
        for (int kk = 0; kk < 4; kk++){
            const int kb = kk * 8;
            uint32_t af[2][4];
            #pragma unroll
            for (int mi = 0; mi < 2; mi++){
                const uint32_t* ap = sa + (wm + mi*16 + g)*ASTRIDE + kb + t;
                af[mi][0] = ap[0];
                af[mi][1] = ap[8*ASTRIDE];
                af[mi][2] = ap[4];
                af[mi][3] = ap[8*ASTRIDE + 4];
            }
            #pragma unroll
            for (int ni = 0; ni < 8; ni++){
                const uint32_t* bp = sb + (kb + t)*BSTRIDE + wn + ni*8 + g;
                uint32_t bf[2];
                bf[0] = bp[0];
                bf[1] = bp[4*BSTRIDE];
                mma1688(acc[0][ni], af[0], bf);
                mma1688(acc[1][ni], af[1], bf);
            }
        }
        if (++s >= NSTAGE) s = 0;
    }

    // epilogue: direct stores (float2 per reg-pair), sector-aligned
    #pragma unroll
    for (int mi = 0; mi < 2; mi++){
        const int r0 = m0 + wm + mi*16 + g;
        #pragma unroll
        for (int half = 0; half < 2; half++){
            const int gr = r0 + half*8;
            if (gr < M){
                #pragma unroll
                for (int ni = 0; ni < 8; ni++){
                    const int col = n0 + wn + ni*8 + t*2;
                    float2 bb = *(const float2*)(bias + col);
                    float v0 = acc[mi][ni][half*2 + 0] + bb.x;
                    float v1 = acc[mi][ni][half*2 + 1] + bb.y;
                    if (EPI == 1){
                        v0 = 0.5f*v0*(1.f + erff(v0*0.70710678118654752f));
                        v1 = 0.5f*v1*(1.f + erff(v1*0.70710678118654752f));
                    }
                    if (EPI == 2){
                        float2 rr = *(const float2*)(Res + (size_t)gr*N + col);
                        v0 += rr.x; v1 += rr.y;
                    }
                    *(float2*)(C + (size_t)gr*N + col) = make_float2(v0, v1);
                }
            }
        }
    }
}

// ---------------- attention via tensor cores ----------------
// one block (128 thr, 4 warps) per (window, head); 49 tokens padded to 64.
// S = Q@K^T (tf32 MMA) + bias + mask -> softmax -> O = P@V (tf32 MMA)
#define QST 36
#define SST 68
__global__ __launch_bounds__(128) void attn_kernel(const float* __restrict__ relt)
{
    __shared__ float Qs[64][QST];
    __shared__ float Ks[64][QST];
    __shared__ float Vs[64][QST];
    __shared__ float Ss[64][SST];

    const int tid = threadIdx.x;
    const int warp = tid >> 5, lane = tid & 31;
    const int g = lane >> 2, t = lane & 3;
    const int wh  = blockIdx.x;
    const int win = wh >> 3;
    const int h   = wh & 7;

    const float* base = g_qkv + (size_t)win*NTOK*(3*DIM) + h*HD;
    const float scale = 0.17677669529663687f;   // 1/sqrt(32)
    for (int e = tid; e < 64*HD; e += 128) {
        int n = e >> 5, d = e & 31;
        if (n < NTOK){
            const float* row = base + (size_t)n*(3*DIM);
            Qs[n][d] = row[d] * scale;
            Ks[n][d] = row[DIM + d];
            Vs[n][d] = row[2*DIM + d];
        } else {
            Qs[n][d] = 0.f; Ks[n][d] = 0.f; Vs[n][d] = 0.f;
        }
    }
    __syncthreads();

    // ---- S = Q @ K^T : warp computes rows 16*warp..16*warp+15, cols 0..63
    float accs[8][4];
    #pragma unroll
    for (int ni = 0; ni < 8; ni++)
        #pragma unroll
        for (int q = 0; q < 4; q++) accs[ni][q] = 0.f;

    #pragma unroll
    for (int kk = 0; kk < 4; kk++){
        const int kb = kk * 8;
        uint32_t a[4];
        a[0] = __float_as_uint(Qs[16*warp + g][kb + t]);
        a[1] = __float_as_uint(Qs[16*warp + 8 + g][kb + t]);
        a[2] = __float_as_uint(Qs[16*warp + g][kb + t + 4]);
        a[3] = __float_as_uint(Qs[16*warp + 8 + g][kb + t + 4]);
        #pragma unroll
        for (int ni = 0; ni < 8; ni++){
            uint32_t b[2];
            b[0] = __float_as_uint(Ks[ni*8 + g][kb + t]);
            b[1] = __float_as_uint(Ks[ni*8 + g][kb + t + 4]);
            mma1688(accs[ni], a, b);
        }
    }

    // ---- S epilogue: rel-bias + shift mask, store to Ss
    const int w  = win % NWIN;
    const int wr = w / 9, wc = w - (w/9)*9;
    #pragma unroll
    for (int ni = 0; ni < 8; ni++){
        #pragma unroll
        for (int half = 0; half < 2; half++){
            int row = 16*warp + half*8 + g;
            int c0 = ni*8 + t*2;
            float v0 = accs[ni][half*2 + 0];
            float v1 = accs[ni][half*2 + 1];
            if (row < NTOK){
                int in_ = row/7, jn = row - (row/7)*7;
                int rn = region_label(wr*7 + in_)*3 + region_label(wc*7 + jn);
                if (c0 < NTOK){
                    int im = c0/7, jm = c0 - (c0/7)*7;
                    v0 += __ldg(&relt[((in_ - im + 6)*13 + (jn - jm + 6))*NHEAD + h]);
                    int rm = region_label(wr*7 + im)*3 + region_label(wc*7 + jm);
                    if (rn != rm) v0 -= 100.f;
                }
                if (c0 + 1 < NTOK){
                    int c1 = c0 + 1;
                    int im = c1/7, jm = c1 - (c1/7)*7;
                    v1 += __ldg(&relt[((in_ - im + 6)*13 + (jn - jm + 6))*NHEAD + h]);
                    int rm = region_label(wr*7 + im)*3 + region_label(wc*7 + jm);
                    if (rn != rm) v1 -= 100.f;
                }
            }
            Ss[row][c0]     = v0;
            Ss[row][c0 + 1] = v1;
        }
    }
    __syncthreads();

    // ---- softmax over valid rows/cols
    if (tid < NTOK){
        float mx = -1e30f;
        #pragma unroll
        for (int m = 0; m < NTOK; m++) mx = fmaxf(mx, Ss[tid][m]);
        float s = 0.f;
        #pragma unroll
        for (int m = 0; m < NTOK; m++){ float e = __expf(Ss[tid][m] - mx); Ss[tid][m] = e; s += e; }
        float inv = 1.f / s;
        #pragma unroll
        for (int m = 0; m < NTOK; m++) Ss[tid][m] *= inv;
        #pragma unroll
        for (int m = NTOK; m < 64; m++) Ss[tid][m] = 0.f;
    }
    __syncthreads();

    // ---- O = P @ V : warp rows 16*warp..+15, cols 0..31
    float acco[4][4];
    #pragma unroll
    for (int ni = 0; ni < 4; ni++)
        #pragma unroll
        for (int q = 0; q < 4; q++) acco[ni][q] = 0.f;

    #pragma unroll
    for (int kk = 0; kk < 8; kk++){
        const int kb = kk * 8;
        uint32_t a[4];
        a[0] = __float_as_uint(Ss[16*warp + g][kb + t]);
        a[1] = __float_as_uint(Ss[16*warp + 8 + g][kb + t]);
        a[2] = __float_as_uint(Ss[16*warp + g][kb + t + 4]);
        a[3] = __float_as_uint(Ss[16*warp + 8 + g][kb + t + 4]);
        #pragma unroll
        for (int ni = 0; ni < 4; ni++){
            uint32_t b[2];
            b[0] = __float_as_uint(Vs[kb + t][ni*8 + g]);
            b[1] = __float_as_uint(Vs[kb + t + 4][ni*8 + g]);
            mma1688(acco[ni], a, b);
        }
    }

    // ---- write O
    float* out = g_att + (size_t)win*NTOK*DIM + h*HD;
    #pragma unroll
    for (int ni = 0; ni < 4; ni++){
        #pragma unroll
        for (int half = 0; half < 2; half++){
            int row = 16*warp + half*8 + g;
            if (row < NTOK){
                int col = ni*8 + t*2;
                *(float2*)(out + (size_t)row*DIM + col) =
                    make_float2(acco[ni][half*2 + 0], acco[ni][half*2 + 1]);
            }
        }
    }
}

// ---------------- host launcher ----------------
extern "C" void kernel_launch(void* const* d_in, const int* in_sizes, int n_in,
                              void* d_out, int out_size)
{
    (void)in_sizes; (void)n_in; (void)out_size;
    const float* x      = (const float*)d_in[0];
    const float* g1     = (const float*)d_in[1];
    const float* b1     = (const float*)d_in[2];
    const float* w_qkv  = (const float*)d_in[3];
    const float* b_qkv  = (const float*)d_in[4];
    const float* relt   = (const float*)d_in[5];
    const float* w_proj = (const float*)d_in[6];
    const float* b_proj = (const float*)d_in[7];
    const float* g2     = (const float*)d_in[8];
    const float* b2     = (const float*)d_in[9];
    const float* w_fc1  = (const float*)d_in[10];
    const float* b_fc1  = (const float*)d_in[11];
    const float* w_fc2  = (const float*)d_in[12];
    const float* b_fc2  = (const float*)d_in[13];
    float* out = (float*)d_out;

    float *p_xw, *p_qkv, *p_att, *p_x1, *p_y, *p_h;
    cudaGetSymbolAddress((void**)&p_xw,  g_xw);
    cudaGetSymbolAddress((void**)&p_qkv, g_qkv);
    cudaGetSymbolAddress((void**)&p_att, g_att);
    cudaGetSymbolAddress((void**)&p_x1,  g_x1);
    cudaGetSymbolAddress((void**)&p_y,   g_y);
    cudaGetSymbolAddress((void**)&p_h,   g_h);

    cudaFuncSetAttribute(tc_gemm<0>, cudaFuncAttributeMaxDynamicSharedMemorySize, GEMM_SMEM);
    cudaFuncSetAttribute(tc_gemm<1>, cudaFuncAttributeMaxDynamicSharedMemorySize, GEMM_SMEM);
    cudaFuncSetAttribute(tc_gemm<2>, cudaFuncAttributeMaxDynamicSharedMemorySize, GEMM_SMEM);

    // 1) LN1 + pad + shift + window partition
    ln1_window_kernel<<<(MW*32 + 255)/256, 256>>>(x, g1, b1);

    // 2) QKV GEMM [MW,256]x[256,768]
    tc_gemm<0><<<dim3(768/BN, (MW + BM - 1)/BM), 256, GEMM_SMEM>>>(
        p_xw, w_qkv, b_qkv, (const float*)0, p_qkv, MW, 768, 256);

    // 3) attention (tensor-core)
    attn_kernel<<<BATCH*NWIN*NHEAD, 128>>>(relt);

    // 4) proj GEMM [MW,256]x[256,256] -> g_xw
    tc_gemm<0><<<dim3(256/BN, (MW + BM - 1)/BM), 256, GEMM_SMEM>>>(
        p_att, w_proj, b_proj, (const float*)0, p_xw, MW, 256, 256);

    // 5) window reverse + unshift + residual + LN2 (fused)
    resid_ln2_kernel<<<(MT*32 + 255)/256, 256>>>(x, g2, b2);

    // 6) fc1 + GELU [MT,256]x[256,1024]
    tc_gemm<1><<<dim3(1024/BN, MT/BM), 256, GEMM_SMEM>>>(
        p_y, w_fc1, b_fc1, (const float*)0, p_h, MT, 1024, 256);

    // 7) fc2 + bias + residual -> out [MT,1024]x[1024,256]
    tc_gemm<2><<<dim3(256/BN, MT/BM), 256, GEMM_SMEM>>>(
        p_h, w_fc2, b_fc2, p_x1, out, MT, 256, 1024);
}

// round 9
// speedup vs baseline: 4.2839x; 1.3729x over previous
#include <cuda_runtime.h>
#include <cuda_fp16.h>
#include <math.h>
#include <stdint.h>

// ---------------- static config ----------------
#define BATCH 24
#define HH 60
#define WW 60
#define HP 63
#define WSZ 7
#define SSZ 3
#define NWIN 81          // 9x9 windows
#define NTOK 49          // tokens per window
#define DIM 256
#define NHEAD 8
#define HD 32
#define MW (BATCH*NWIN*NTOK)   // 95256 window tokens
#define MT (BATCH*HH*WW)       // 86400 real tokens

// GEMM tiling (mma.sync m16n8k16 fp16)
#define BM 128
#define BN 128
#define BK 32
#define AH 40                  // A smem row stride (halves) — LDSM conflict-free
#define BH 136                 // B smem row stride (halves) — LDSM.T conflict-free
#define STGH (BM*AH + BK*BH)   // halves per stage = 5120 + 4352 = 9472
#define NSTAGE 3
#define GEMM_SMEM (NSTAGE*STGH*2)   // 56832 bytes

// ---------------- scratch (static device globals) ----------------
__device__ __half g_xh [(size_t)MW*DIM];      // LN1 windowed output (fp16)
__device__ float  g_qkv[(size_t)MW*3*DIM];    // qkv (fp32, read by attention)
__device__ __half g_atth[(size_t)MW*DIM];     // attention output (fp16)
__device__ float  g_proj[(size_t)MW*DIM];     // proj output (fp32, window layout)
__device__ float  g_x1 [(size_t)MT*DIM];      // x + attn branch
__device__ __half g_yh [(size_t)MT*DIM];      // LN2 output (fp16)
__device__ __half g_hh [(size_t)MT*4*DIM];    // fc1 output (fp16)
// fp16 weights
__device__ __half g_wq[256*768];
__device__ __half g_wp[256*256];
__device__ __half g_w1[256*1024];
__device__ __half g_w2[1024*256];

// ---------------- helpers ----------------
__device__ __forceinline__ uint32_t smem_u32(const void* p){
    return (uint32_t)__cvta_generic_to_shared((void*)p);
}
__device__ __forceinline__ void ldsm4(uint32_t* r, uint32_t addr){
    asm volatile("ldmatrix.sync.aligned.m8n8.x4.shared.b16 {%0,%1,%2,%3}, [%4];"
        : "=r"(r[0]),"=r"(r[1]),"=r"(r[2]),"=r"(r[3]) : "r"(addr));
}
__device__ __forceinline__ void ldsm4t(uint32_t* r, uint32_t addr){
    asm volatile("ldmatrix.sync.aligned.m8n8.x4.trans.shared.b16 {%0,%1,%2,%3}, [%4];"
        : "=r"(r[0]),"=r"(r[1]),"=r"(r[2]),"=r"(r[3]) : "r"(addr));
}
__device__ __forceinline__ void mma16816(float* c, const uint32_t* a, uint32_t b0, uint32_t b1){
    asm volatile("mma.sync.aligned.m16n8k16.row.col.f32.f16.f16.f32 "
        "{%0,%1,%2,%3}, {%4,%5,%6,%7}, {%8,%9}, {%0,%1,%2,%3};"
        : "+f"(c[0]),"+f"(c[1]),"+f"(c[2]),"+f"(c[3])
        : "r"(a[0]),"r"(a[1]),"r"(a[2]),"r"(a[3]), "r"(b0),"r"(b1));
}
__device__ __forceinline__ void mma1688(float* c, const uint32_t* a, const uint32_t* b){
    asm volatile("mma.sync.aligned.m16n8k8.row.col.f32.tf32.tf32.f32 "
        "{%0,%1,%2,%3}, {%4,%5,%6,%7}, {%8,%9}, {%0,%1,%2,%3};"
        : "+f"(c[0]),"+f"(c[1]),"+f"(c[2]),"+f"(c[3])
        : "r"(a[0]),"r"(a[1]),"r"(a[2]),"r"(a[3]), "r"(b[0]),"r"(b[1]));
}
__device__ __forceinline__ void cp16(uint32_t saddr, const void* g, int sz){
    asm volatile("cp.async.cg.shared.global [%0], [%1], 16, %2;"
                 :: "r"(saddr), "l"(g), "r"(sz) : "memory");
}
__device__ __forceinline__ float warp_sum(float v){
    #pragma unroll
    for (int o = 16; o; o >>= 1) v += __shfl_xor_sync(0xffffffffu, v, o);
    return v;
}
__device__ __forceinline__ int region_label(int p){
    return p < (HP - WSZ) ? 0 : (p < (HP - SSZ) ? 1 : 2);
}

// ---------------- fp32 -> fp16 weight conversion ----------------
__global__ void f2h_kernel(const float* __restrict__ s, __half* __restrict__ d, int n2){
    int i = blockIdx.x*blockDim.x + threadIdx.x;
    if (i < n2){
        float2 v = ((const float2*)s)[i];
        ((__half2*)d)[i] = __floats2half2_rn(v.x, v.y);
    }
}

// ---------------- LN1 + pad + shift + window partition (fp16 out) ----------------
__global__ __launch_bounds__(256) void ln1_window_kernel(
    const float* __restrict__ x, const float* __restrict__ g, const float* __restrict__ b)
{
    int warp = (blockIdx.x * blockDim.x + threadIdx.x) >> 5;
    int lane = threadIdx.x & 31;
    if (warp >= MW) return;
    int bi  = warp / (NWIN*NTOK);
    int rem = warp - bi*(NWIN*NTOK);
    int w = rem / NTOK, n = rem - w*NTOK;
    int r = w/9, c = w - r*9, i = n/7, j = n - i*7;
    int hs = r*7 + i + SSZ; if (hs >= HP) hs -= HP;
    int ws = c*7 + j + SSZ; if (ws >= HP) ws -= HP;

    __half2* dst = (__half2*)(g_xh + (size_t)warp*DIM);
    if (hs >= HH || ws >= WW) {
        __half2 z = __floats2half2_rn(0.f, 0.f);
        dst[lane*2] = z; dst[lane*2+1] = z;
        dst[64+lane*2] = z; dst[64+lane*2+1] = z;
        return;
    }
    const float4* src = (const float4*)(x + ((size_t)bi*(HH*WW) + hs*WW + ws)*DIM);
    float4 v0 = src[lane], v1 = src[lane+32];
    float s  = v0.x+v0.y+v0.z+v0.w + v1.x+v1.y+v1.z+v1.w;
    float ss = v0.x*v0.x+v0.y*v0.y+v0.z*v0.z+v0.w*v0.w
             + v1.x*v1.x+v1.y*v1.y+v1.z*v1.z+v1.w*v1.w;
    s  = warp_sum(s);
    ss = warp_sum(ss);
    float mu   = s * (1.f/DIM);
    float var  = ss * (1.f/DIM) - mu*mu;
    float rstd = rsqrtf(var + 1e-5f);
    const float4* gv = (const float4*)g;
    const float4* bv = (const float4*)b;
    float4 g0 = gv[lane], g1 = gv[lane+32], b0 = bv[lane], b1 = bv[lane+32];
    dst[lane*2]      = __floats2half2_rn((v0.x-mu)*rstd*g0.x + b0.x, (v0.y-mu)*rstd*g0.y + b0.y);
    dst[lane*2+1]    = __floats2half2_rn((v0.z-mu)*rstd*g0.z + b0.z, (v0.w-mu)*rstd*g0.w + b0.w);
    dst[64+lane*2]   = __floats2half2_rn((v1.x-mu)*rstd*g1.x + b1.x, (v1.y-mu)*rstd*g1.y + b1.y);
    dst[64+lane*2+1] = __floats2half2_rn((v1.z-mu)*rstd*g1.z + b1.z, (v1.w-mu)*rstd*g1.w + b1.w);
}

// ---------------- window reverse + unshift + residual + LN2 (fused) ----------------
__global__ __launch_bounds__(256) void resid_ln2_kernel(
    const float* __restrict__ x, const float* __restrict__ g, const float* __restrict__ b)
{
    int warp = (blockIdx.x * blockDim.x + threadIdx.x) >> 5;
    int lane = threadIdx.x & 31;
    if (warp >= MT) return;
    int bi = warp / (HH*WW), l = warp - bi*(HH*WW);
    int hh = l / WW, ww = l - hh*WW;
    int hs = hh + (HP - SSZ); if (hs >= HP) hs -= HP;
    int ws = ww + (HP - SSZ); if (ws >= HP) ws -= HP;
    int r = hs/7, i = hs - r*7, c = ws/7, j = ws - c*7;
    size_t m = ((size_t)bi*NWIN + r*9 + c)*NTOK + i*7 + j;

    const float4* xs = (const float4*)(x + (size_t)warp*DIM);
    const float4* ps = (const float4*)(g_proj + m*DIM);
    float4 a0 = xs[lane], a1 = xs[lane+32];
    float4 p0 = ps[lane], p1 = ps[lane+32];
    a0.x += p0.x; a0.y += p0.y; a0.z += p0.z; a0.w += p0.w;
    a1.x += p1.x; a1.y += p1.y; a1.z += p1.z; a1.w += p1.w;
    float4* x1 = (float4*)(g_x1 + (size_t)warp*DIM);
    x1[lane] = a0; x1[lane+32] = a1;

    float s  = a0.x+a0.y+a0.z+a0.w + a1.x+a1.y+a1.z+a1.w;
    float ss = a0.x*a0.x+a0.y*a0.y+a0.z*a0.z+a0.w*a0.w
             + a1.x*a1.x+a1.y*a1.y+a1.z*a1.z+a1.w*a1.w;
    s  = warp_sum(s);
    ss = warp_sum(ss);
    float mu   = s * (1.f/DIM);
    float var  = ss * (1.f/DIM) - mu*mu;
    float rstd = rsqrtf(var + 1e-5f);
    const float4* gv = (const float4*)g;
    const float4* bv = (const float4*)b;
    float4 g0 = gv[lane], g1 = gv[lane+32], b0 = bv[lane], b1 = bv[lane+32];
    __half2* dst = (__half2*)(g_yh + (size_t)warp*DIM);
    dst[lane*2]      = __floats2half2_rn((a0.x-mu)*rstd*g0.x + b0.x, (a0.y-mu)*rstd*g0.y + b0.y);
    dst[lane*2+1]    = __floats2half2_rn((a0.z-mu)*rstd*g0.z + b0.z, (a0.w-mu)*rstd*g0.w + b0.w);
    dst[64+lane*2]   = __floats2half2_rn((a1.x-mu)*rstd*g1.x + b1.x, (a1.y-mu)*rstd*g1.y + b1.y);
    dst[64+lane*2+1] = __floats2half2_rn((a1.z-mu)*rstd*g1.z + b1.z, (a1.w-mu)*rstd*g1.w + b1.w);
}

// ---------------- fp16 mma.sync GEMM, 3-stage cp.async + ldmatrix ----------------
// C[M,N] = A[M,K](fp16) @ B[K,N](fp16) (+bias) ; EPI: 0=bias, 1=bias+gelu, 2=bias+res
template<int EPI, typename TOUT>
__global__ __launch_bounds__(256, 2) void hgemm(
    const __half* __restrict__ A, const __half* __restrict__ B,
    const float* __restrict__ bias, const float* __restrict__ Res,
    TOUT* __restrict__ C, int M, int N, int K)
{
    extern __shared__ __half sm[];
    const int tid = threadIdx.x;
    const int m0 = blockIdx.y * BM, n0 = blockIdx.x * BN;
    const int lane = tid & 31, warp = tid >> 5;
    const int wm = (warp >> 1) * 32;     // 4 warps along M
    const int wn = (warp & 1) * 64;      // 2 warps along N
    const int g = lane >> 2, t = lane & 3;
    const int lr = lane & 15, lc = lane >> 4;   // ldmatrix row / col-block

    float acc[2][8][4];
    #pragma unroll
    for (int mi = 0; mi < 2; mi++)
        #pragma unroll
        for (int ni = 0; ni < 8; ni++)
            #pragma unroll
            for (int q = 0; q < 4; q++) acc[mi][ni][q] = 0.f;

    const uint32_t sbase = smem_u32(sm);

    auto issue = [&](int kc, int s){
        const int k0 = kc * BK;
        // A tile: 128 rows x 32 halves = 4 x 16B chunks/row
        #pragma unroll
        for (int i = 0; i < 2; i++){
            int f = tid + i*256;
            int row = f >> 2, q = f & 3;
            int gr = m0 + row;
            int cl = gr < M ? gr : (M - 1);
            const __half* src = A + (size_t)cl*K + k0 + q*8;
            cp16(sbase + (uint32_t)((s*STGH + row*AH + q*8)*2), src, gr < M ? 16 : 0);
        }
        // B tile: 32 rows x 128 halves = 16 x 16B chunks/row
        #pragma unroll
        for (int i = 0; i < 2; i++){
            int f = tid + i*256;
            int row = f >> 4, q = f & 15;
            const __half* src = B + (size_t)(k0 + row)*N + n0 + q*8;
            cp16(sbase + (uint32_t)((s*STGH + BM*AH + row*BH + q*8)*2), src, 16);
        }
        asm volatile("cp.async.commit_group;" ::: "memory");
    };

    const int nch = K / BK;
    issue(0, 0);
    if (nch > 1) issue(1, 1);
    int s = 0;
    for (int kc = 0; kc < nch; kc++){
        if (kc + 1 < nch){
            asm volatile("cp.async.wait_group 1;" ::: "memory");
        } else {
            asm volatile("cp.async.wait_group 0;" ::: "memory");
        }
        __syncthreads();
        if (kc + 2 < nch){
            int s2 = s + 2; if (s2 >= NSTAGE) s2 -= NSTAGE;
            issue(kc + 2, s2);
        }
        const uint32_t sa = sbase + (uint32_t)(s*STGH)*2;
        const uint32_t sb = sbase + (uint32_t)(s*STGH + BM*AH)*2;
        #pragma unroll
        for (int kk = 0; kk < 2; kk++){
            uint32_t af[2][4];
            #pragma unroll
            for (int mi = 0; mi < 2; mi++)
                ldsm4(af[mi], sa + (uint32_t)(((wm + mi*16 + lr)*AH + kk*16 + lc*8)*2));
            #pragma unroll
            for (int nb = 0; nb < 4; nb++){
                uint32_t bf[4];
                ldsm4t(bf, sb + (uint32_t)(((kk*16 + lr)*BH + wn + nb*16 + lc*8)*2));
                mma16816(acc[0][nb*2+0], af[0], bf[0], bf[1]);
                mma16816(acc[1][nb*2+0], af[1], bf[0], bf[1]);
                mma16816(acc[0][nb*2+1], af[0], bf[2], bf[3]);
                mma16816(acc[1][nb*2+1], af[1], bf[2], bf[3]);
            }
        }
        if (++s >= NSTAGE) s = 0;
    }

    // epilogue
    #pragma unroll
    for (int mi = 0; mi < 2; mi++){
        const int r0 = m0 + wm + mi*16 + g;
        #pragma unroll
        for (int half = 0; half < 2; half++){
            const int gr = r0 + half*8;
            if (gr < M){
                #pragma unroll
                for (int ni = 0; ni < 8; ni++){
                    const int col = n0 + wn + ni*8 + t*2;
                    float2 bb = *(const float2*)(bias + col);
                    float v0 = acc[mi][ni][half*2 + 0] + bb.x;
                    float v1 = acc[mi][ni][half*2 + 1] + bb.y;
                    if (EPI == 1){
                        v0 = 0.5f*v0*(1.f + erff(v0*0.70710678118654752f));
                        v1 = 0.5f*v1*(1.f + erff(v1*0.70710678118654752f));
                    }
                    if (EPI == 2){
                        float2 rr = *(const float2*)(Res + (size_t)gr*N + col);
                        v0 += rr.x; v1 += rr.y;
                    }
                    if (sizeof(TOUT) == 2){
                        *(__half2*)((__half*)C + (size_t)gr*N + col) = __floats2half2_rn(v0, v1);
                    } else {
                        *(float2*)((float*)C + (size_t)gr*N + col) = make_float2(v0, v1);
                    }
                }
            }
        }
    }
}

// ---------------- attention via tensor cores (tf32), fp16 output ----------------
#define QST 36
#define SST 68
__global__ __launch_bounds__(128) void attn_kernel(const float* __restrict__ relt)
{
    __shared__ float Qs[64][QST];
    __shared__ float Ks[64][QST];
    __shared__ float Vs[64][QST];
    __shared__ float Ss[64][SST];

    const int tid = threadIdx.x;
    const int warp = tid >> 5, lane = tid & 31;
    const int g = lane >> 2, t = lane & 3;
    const int wh  = blockIdx.x;
    const int win = wh >> 3;
    const int h   = wh & 7;

    const float* base = g_qkv + (size_t)win*NTOK*(3*DIM) + h*HD;
    const float scale = 0.17677669529663687f;   // 1/sqrt(32)
    for (int e = tid; e < 64*HD; e += 128) {
        int n = e >> 5, d = e & 31;
        if (n < NTOK){
            const float* row = base + (size_t)n*(3*DIM);
            Qs[n][d] = row[d] * scale;
            Ks[n][d] = row[DIM + d];
            Vs[n][d] = row[2*DIM + d];
        } else {
            Qs[n][d] = 0.f; Ks[n][d] = 0.f; Vs[n][d] = 0.f;
        }
    }
    __syncthreads();

    float accs[8][4];
    #pragma unroll
    for (int ni = 0; ni < 8; ni++)
        #pragma unroll
        for (int q = 0; q < 4; q++) accs[ni][q] = 0.f;

    #pragma unroll
    for (int kk = 0; kk < 4; kk++){
        const int kb = kk * 8;
        uint32_t a[4];
        a[0] = __float_as_uint(Qs[16*warp + g][kb + t]);
        a[1] = __float_as_uint(Qs[16*warp + 8 + g][kb + t]);
        a[2] = __float_as_uint(Qs[16*warp + g][kb + t + 4]);
        a[3] = __float_as_uint(Qs[16*warp + 8 + g][kb + t + 4]);
        #pragma unroll
        for (int ni = 0; ni < 8; ni++){
            uint32_t b[2];
            b[0] = __float_as_uint(Ks[ni*8 + g][kb + t]);
            b[1] = __float_as_uint(Ks[ni*8 + g][kb + t + 4]);
            mma1688(accs[ni], a, b);
        }
    }

    const int w  = win % NWIN;
    const int wr = w / 9, wc = w - (w/9)*9;
    #pragma unroll
    for (int ni = 0; ni < 8; ni++){
        #pragma unroll
        for (int half = 0; half < 2; half++){
            int row = 16*warp + half*8 + g;
            int c0 = ni*8 + t*2;
            float v0 = accs[ni][half*2 + 0];
            float v1 = accs[ni][half*2 + 1];
            if (row < NTOK){
                int in_ = row/7, jn = row - (row/7)*7;
                int rn = region_label(wr*7 + in_)*3 + region_label(wc*7 + jn);
                if (c0 < NTOK){
                    int im = c0/7, jm = c0 - (c0/7)*7;
                    v0 += __ldg(&relt[((in_ - im + 6)*13 + (jn - jm + 6))*NHEAD + h]);
                    int rm = region_label(wr*7 + im)*3 + region_label(wc*7 + jm);
                    if (rn != rm) v0 -= 100.f;
                }
                if (c0 + 1 < NTOK){
                    int c1 = c0 + 1;
                    int im = c1/7, jm = c1 - (c1/7)*7;
                    v1 += __ldg(&relt[((in_ - im + 6)*13 + (jn - jm + 6))*NHEAD + h]);
                    int rm = region_label(wr*7 + im)*3 + region_label(wc*7 + jm);
                    if (rn != rm) v1 -= 100.f;
                }
            }
            Ss[row][c0]     = v0;
            Ss[row][c0 + 1] = v1;
        }
    }
    __syncthreads();

    if (tid < NTOK){
        float mx = -1e30f;
        #pragma unroll
        for (int m = 0; m < NTOK; m++) mx = fmaxf(mx, Ss[tid][m]);
        float s = 0.f;
        #pragma unroll
        for (int m = 0; m < NTOK; m++){ float e = __expf(Ss[tid][m] - mx); Ss[tid][m] = e; s += e; }
        float inv = 1.f / s;
        #pragma unroll
        for (int m = 0; m < NTOK; m++) Ss[tid][m] *= inv;
        #pragma unroll
        for (int m = NTOK; m < 64; m++) Ss[tid][m] = 0.f;
    }
    __syncthreads();

    float acco[4][4];
    #pragma unroll
    for (int ni = 0; ni < 4; ni++)
        #pragma unroll
        for (int q = 0; q < 4; q++) acco[ni][q] = 0.f;

    #pragma unroll
    for (int kk = 0; kk < 8; kk++){
        const int kb = kk * 8;
        uint32_t a[4];
        a[0] = __float_as_uint(Ss[16*warp + g][kb + t]);
        a[1] = __float_as_uint(Ss[16*warp + 8 + g][kb + t]);
        a[2] = __float_as_uint(Ss[16*warp + g][kb + t + 4]);
        a[3] = __float_as_uint(Ss[16*warp + 8 + g][kb + t + 4]);
        #pragma unroll
        for (int ni = 0; ni < 4; ni++){
            uint32_t b[2];
            b[0] = __float_as_uint(Vs[kb + t][ni*8 + g]);
            b[1] = __float_as_uint(Vs[kb + t + 4][ni*8 + g]);
            mma1688(acco[ni], a, b);
        }
    }

    __half* out = g_atth + (size_t)win*NTOK*DIM + h*HD;
    #pragma unroll
    for (int ni = 0; ni < 4; ni++){
        #pragma unroll
        for (int half = 0; half < 2; half++){
            int row = 16*warp + half*8 + g;
            if (row < NTOK){
                int col = ni*8 + t*2;
                *(__half2*)(out + (size_t)row*DIM + col) =
                    __floats2half2_rn(acco[ni][half*2 + 0], acco[ni][half*2 + 1]);
            }
        }
    }
}

// ---------------- host launcher ----------------
extern "C" void kernel_launch(void* const* d_in, const int* in_sizes, int n_in,
                              void* d_out, int out_size)
{
    (void)in_sizes; (void)n_in; (void)out_size;
    const float* x      = (const float*)d_in[0];
    const float* g1     = (const float*)d_in[1];
    const float* b1     = (const float*)d_in[2];
    const float* w_qkv  = (const float*)d_in[3];
    const float* b_qkv  = (const float*)d_in[4];
    const float* relt   = (const float*)d_in[5];
    const float* w_proj = (const float*)d_in[6];
    const float* b_proj = (const float*)d_in[7];
    const float* g2     = (const float*)d_in[8];
    const float* b2     = (const float*)d_in[9];
    const float* w_fc1  = (const float*)d_in[10];
    const float* b_fc1  = (const float*)d_in[11];
    const float* w_fc2  = (const float*)d_in[12];
    const float* b_fc2  = (const float*)d_in[13];
    float* out = (float*)d_out;

    __half *p_xh, *p_atth, *p_yh, *p_hh, *p_wq, *p_wp, *p_w1, *p_w2;
    float *p_qkv, *p_proj, *p_x1;
    cudaGetSymbolAddress((void**)&p_xh,  g_xh);
    cudaGetSymbolAddress((void**)&p_qkv, g_qkv);
    cudaGetSymbolAddress((void**)&p_atth,g_atth);
    cudaGetSymbolAddress((void**)&p_proj,g_proj);
    cudaGetSymbolAddress((void**)&p_x1,  g_x1);
    cudaGetSymbolAddress((void**)&p_yh,  g_yh);
    cudaGetSymbolAddress((void**)&p_hh,  g_hh);
    cudaGetSymbolAddress((void**)&p_wq,  g_wq);
    cudaGetSymbolAddress((void**)&p_wp,  g_wp);
    cudaGetSymbolAddress((void**)&p_w1,  g_w1);
    cudaGetSymbolAddress((void**)&p_w2,  g_w2);

    cudaFuncSetAttribute(hgemm<0,float>,  cudaFuncAttributeMaxDynamicSharedMemorySize, GEMM_SMEM);
    cudaFuncSetAttribute(hgemm<1,__half>, cudaFuncAttributeMaxDynamicSharedMemorySize, GEMM_SMEM);
    cudaFuncSetAttribute(hgemm<2,float>,  cudaFuncAttributeMaxDynamicSharedMemorySize, GEMM_SMEM);

    // 0) weights -> fp16
    f2h_kernel<<<(256*768/2 + 255)/256, 256>>>(w_qkv, p_wq, 256*768/2);
    f2h_kernel<<<(256*256/2 + 255)/256, 256>>>(w_proj, p_wp, 256*256/2);
    f2h_kernel<<<(256*1024/2 + 255)/256, 256>>>(w_fc1, p_w1, 256*1024/2);
    f2h_kernel<<<(1024*256/2 + 255)/256, 256>>>(w_fc2, p_w2, 1024*256/2);

    // 1) LN1 + pad + shift + window partition (fp16)
    ln1_window_kernel<<<(MW*32 + 255)/256, 256>>>(x, g1, b1);

    // 2) QKV GEMM [MW,256]x[256,768] -> fp32
    hgemm<0,float><<<dim3(768/BN, (MW + BM - 1)/BM), 256, GEMM_SMEM>>>(
        p_xh, p_wq, b_qkv, (const float*)0, p_qkv, MW, 768, 256);

    // 3) attention -> fp16
    attn_kernel<<<BATCH*NWIN*NHEAD, 128>>>(relt);

    // 4) proj GEMM [MW,256]x[256,256] -> fp32
    hgemm<0,float><<<dim3(256/BN, (MW + BM - 1)/BM), 256, GEMM_SMEM>>>(
        p_atth, p_wp, b_proj, (const float*)0, p_proj, MW, 256, 256);

    // 5) window reverse + unshift + residual + LN2
    resid_ln2_kernel<<<(MT*32 + 255)/256, 256>>>(x, g2, b2);

    // 6) fc1 + GELU [MT,256]x[256,1024] -> fp16
    hgemm<1,__half><<<dim3(1024/BN, MT/BM), 256, GEMM_SMEM>>>(
        p_yh, p_w1, b_fc1, (const float*)0, p_hh, MT, 1024, 256);

    // 7) fc2 + bias + residual [MT,1024]x[1024,256] -> out fp32
    hgemm<2,float><<<dim3(256/BN, MT/BM), 256, GEMM_SMEM>>>(
        p_hh, p_w2, b_fc2, p_x1, out, MT, 256, 1024);
}

// round 10
// speedup vs baseline: 4.8190x; 1.1249x over previous
#include <cuda_runtime.h>
#include <cuda_fp16.h>
#include <math.h>
#include <stdint.h>

// ---------------- static config ----------------
#define BATCH 24
#define HH 60
#define WW 60
#define HP 63
#define WSZ 7
#define SSZ 3
#define NWIN 81          // 9x9 windows
#define NTOK 49          // tokens per window
#define DIM 256
#define NHEAD 8
#define HD 32
#define MW (BATCH*NWIN*NTOK)   // 95256 window tokens
#define MT (BATCH*HH*WW)       // 86400 real tokens

// GEMM tiling (mma.sync m16n8k16 fp16)
#define BM 128
#define BN 128
#define BK 32
#define AH 40                  // A smem row stride (halves) — LDSM conflict-free
#define BH 136                 // B smem row stride (halves) — LDSM.T conflict-free
#define STGH (BM*AH + BK*BH)   // halves per stage = 5120 + 4352 = 9472
#define NSTAGE 3
#define GEMM_SMEM (NSTAGE*STGH*2)   // 56832 bytes

// ---------------- scratch (static device globals) ----------------
__device__ __half g_xh  [(size_t)MW*DIM];     // LN1 windowed output (fp16)
__device__ __half g_qkvh[(size_t)MW*3*DIM];   // qkv (fp16)
__device__ __half g_atth[(size_t)MW*DIM];     // attention output (fp16)
__device__ float  g_proj[(size_t)MW*DIM];     // proj output (fp32, window layout)
__device__ float  g_x1  [(size_t)MT*DIM];     // x + attn branch
__device__ __half g_yh  [(size_t)MT*DIM];     // LN2 output (fp16)
__device__ __half g_hh  [(size_t)MT*4*DIM];   // fc1 output (fp16)
// fp16 weights
__device__ __half g_wq[256*768];
__device__ __half g_wp[256*256];
__device__ __half g_w1[256*1024];
__device__ __half g_w2[1024*256];

// ---------------- helpers ----------------
__device__ __forceinline__ uint32_t smem_u32(const void* p){
    return (uint32_t)__cvta_generic_to_shared((void*)p);
}
__device__ __forceinline__ void ldsm4(uint32_t* r, uint32_t addr){
    asm volatile("ldmatrix.sync.aligned.m8n8.x4.shared.b16 {%0,%1,%2,%3}, [%4];"
        : "=r"(r[0]),"=r"(r[1]),"=r"(r[2]),"=r"(r[3]) : "r"(addr));
}
__device__ __forceinline__ void ldsm4t(uint32_t* r, uint32_t addr){
    asm volatile("ldmatrix.sync.aligned.m8n8.x4.trans.shared.b16 {%0,%1,%2,%3}, [%4];"
        : "=r"(r[0]),"=r"(r[1]),"=r"(r[2]),"=r"(r[3]) : "r"(addr));
}
__device__ __forceinline__ void mma16816(float* c, const uint32_t* a, uint32_t b0, uint32_t b1){
    asm volatile("mma.sync.aligned.m16n8k16.row.col.f32.f16.f16.f32 "
        "{%0,%1,%2,%3}, {%4,%5,%6,%7}, {%8,%9}, {%0,%1,%2,%3};"
        : "+f"(c[0]),"+f"(c[1]),"+f"(c[2]),"+f"(c[3])
        : "r"(a[0]),"r"(a[1]),"r"(a[2]),"r"(a[3]), "r"(b0),"r"(b1));
}
__device__ __forceinline__ void cp16(uint32_t saddr, const void* g, int sz){
    asm volatile("cp.async.cg.shared.global [%0], [%1], 16, %2;"
                 :: "r"(saddr), "l"(g), "r"(sz) : "memory");
}
__device__ __forceinline__ float warp_sum(float v){
    #pragma unroll
    for (int o = 16; o; o >>= 1) v += __shfl_xor_sync(0xffffffffu, v, o);
    return v;
}
__device__ __forceinline__ int region_label(int p){
    return p < (HP - WSZ) ? 0 : (p < (HP - SSZ) ? 1 : 2);
}

// ---------------- fp32 -> fp16 weight conversion ----------------
__global__ void f2h_kernel(const float* __restrict__ s, __half* __restrict__ d, int n2){
    int i = blockIdx.x*blockDim.x + threadIdx.x;
    if (i < n2){
        float2 v = ((const float2*)s)[i];
        ((__half2*)d)[i] = __floats2half2_rn(v.x, v.y);
    }
}

// ---------------- LN1 + pad + shift + window partition (fp16 out) ----------------
__global__ __launch_bounds__(256) void ln1_window_kernel(
    const float* __restrict__ x, const float* __restrict__ g, const float* __restrict__ b)
{
    int warp = (blockIdx.x * blockDim.x + threadIdx.x) >> 5;
    int lane = threadIdx.x & 31;
    if (warp >= MW) return;
    int bi  = warp / (NWIN*NTOK);
    int rem = warp - bi*(NWIN*NTOK);
    int w = rem / NTOK, n = rem - w*NTOK;
    int r = w/9, c = w - r*9, i = n/7, j = n - i*7;
    int hs = r*7 + i + SSZ; if (hs >= HP) hs -= HP;
    int ws = c*7 + j + SSZ; if (ws >= HP) ws -= HP;

    __half2* dst = (__half2*)(g_xh + (size_t)warp*DIM);
    if (hs >= HH || ws >= WW) {
        __half2 z = __floats2half2_rn(0.f, 0.f);
        dst[lane*2] = z; dst[lane*2+1] = z;
        dst[64+lane*2] = z; dst[64+lane*2+1] = z;
        return;
    }
    const float4* src = (const float4*)(x + ((size_t)bi*(HH*WW) + hs*WW + ws)*DIM);
    float4 v0 = src[lane], v1 = src[lane+32];
    float s  = v0.x+v0.y+v0.z+v0.w + v1.x+v1.y+v1.z+v1.w;
    float ss = v0.x*v0.x+v0.y*v0.y+v0.z*v0.z+v0.w*v0.w
             + v1.x*v1.x+v1.y*v1.y+v1.z*v1.z+v1.w*v1.w;
    s  = warp_sum(s);
    ss = warp_sum(ss);
    float mu   = s * (1.f/DIM);
    float var  = ss * (1.f/DIM) - mu*mu;
    float rstd = rsqrtf(var + 1e-5f);
    const float4* gv = (const float4*)g;
    const float4* bv = (const float4*)b;
    float4 g0 = gv[lane], g1 = gv[lane+32], b0 = bv[lane], b1 = bv[lane+32];
    dst[lane*2]      = __floats2half2_rn((v0.x-mu)*rstd*g0.x + b0.x, (v0.y-mu)*rstd*g0.y + b0.y);
    dst[lane*2+1]    = __floats2half2_rn((v0.z-mu)*rstd*g0.z + b0.z, (v0.w-mu)*rstd*g0.w + b0.w);
    dst[64+lane*2]   = __floats2half2_rn((v1.x-mu)*rstd*g1.x + b1.x, (v1.y-mu)*rstd*g1.y + b1.y);
    dst[64+lane*2+1] = __floats2half2_rn((v1.z-mu)*rstd*g1.z + b1.z, (v1.w-mu)*rstd*g1.w + b1.w);
}

// ---------------- window reverse + unshift + residual + LN2 (fused) ----------------
__global__ __launch_bounds__(256) void resid_ln2_kernel(
    const float* __restrict__ x, const float* __restrict__ g, const float* __restrict__ b)
{
    int warp = (blockIdx.x * blockDim.x + threadIdx.x) >> 5;
    int lane = threadIdx.x & 31;
    if (warp >= MT) return;
    int bi = warp / (HH*WW), l = warp - bi*(HH*WW);
    int hh = l / WW, ww = l - hh*WW;
    int hs = hh + (HP - SSZ); if (hs >= HP) hs -= HP;
    int ws = ww + (HP - SSZ); if (ws >= HP) ws -= HP;
    int r = hs/7, i = hs - r*7, c = ws/7, j = ws - c*7;
    size_t m = ((size_t)bi*NWIN + r*9 + c)*NTOK + i*7 + j;

    const float4* xs = (const float4*)(x + (size_t)warp*DIM);
    const float4* ps = (const float4*)(g_proj + m*DIM);
    float4 a0 = xs[lane], a1 = xs[lane+32];
    float4 p0 = ps[lane], p1 = ps[lane+32];
    a0.x += p0.x; a0.y += p0.y; a0.z += p0.z; a0.w += p0.w;
    a1.x += p1.x; a1.y += p1.y; a1.z += p1.z; a1.w += p1.w;
    float4* x1 = (float4*)(g_x1 + (size_t)warp*DIM);
    x1[lane] = a0; x1[lane+32] = a1;

    float s  = a0.x+a0.y+a0.z+a0.w + a1.x+a1.y+a1.z+a1.w;
    float ss = a0.x*a0.x+a0.y*a0.y+a0.z*a0.z+a0.w*a0.w
             + a1.x*a1.x+a1.y*a1.y+a1.z*a1.z+a1.w*a1.w;
    s  = warp_sum(s);
    ss = warp_sum(ss);
    float mu   = s * (1.f/DIM);
    float var  = ss * (1.f/DIM) - mu*mu;
    float rstd = rsqrtf(var + 1e-5f);
    const float4* gv = (const float4*)g;
    const float4* bv = (const float4*)b;
    float4 g0 = gv[lane], g1 = gv[lane+32], b0 = bv[lane], b1 = bv[lane+32];
    __half2* dst = (__half2*)(g_yh + (size_t)warp*DIM);
    dst[lane*2]      = __floats2half2_rn((a0.x-mu)*rstd*g0.x + b0.x, (a0.y-mu)*rstd*g0.y + b0.y);
    dst[lane*2+1]    = __floats2half2_rn((a0.z-mu)*rstd*g0.z + b0.z, (a0.w-mu)*rstd*g0.w + b0.w);
    dst[64+lane*2]   = __floats2half2_rn((a1.x-mu)*rstd*g1.x + b1.x, (a1.y-mu)*rstd*g1.y + b1.y);
    dst[64+lane*2+1] = __floats2half2_rn((a1.z-mu)*rstd*g1.z + b1.z, (a1.w-mu)*rstd*g1.w + b1.w);
}

// ---------------- fp16 mma.sync GEMM, 3-stage cp.async + ldmatrix ----------------
template<int EPI, typename TOUT>
__global__ __launch_bounds__(256, 2) void hgemm(
    const __half* __restrict__ A, const __half* __restrict__ B,
    const float* __restrict__ bias, const float* __restrict__ Res,
    TOUT* __restrict__ C, int M, int N, int K)
{
    extern __shared__ __half sm[];
    const int tid = threadIdx.x;
    const int m0 = blockIdx.y * BM, n0 = blockIdx.x * BN;
    const int lane = tid & 31, warp = tid >> 5;
    const int wm = (warp >> 1) * 32;     // 4 warps along M
    const int wn = (warp & 1) * 64;      // 2 warps along N
    const int g = lane >> 2, t = lane & 3;
    const int lr = lane & 15, lc = lane >> 4;

    float acc[2][8][4];
    #pragma unroll
    for (int mi = 0; mi < 2; mi++)
        #pragma unroll
        for (int ni = 0; ni < 8; ni++)
            #pragma unroll
            for (int q = 0; q < 4; q++) acc[mi][ni][q] = 0.f;

    const uint32_t sbase = smem_u32(sm);

    auto issue = [&](int kc, int s){
        const int k0 = kc * BK;
        #pragma unroll
        for (int i = 0; i < 2; i++){
            int f = tid + i*256;
            int row = f >> 2, q = f & 3;
            int gr = m0 + row;
            int cl = gr < M ? gr : (M - 1);
            const __half* src = A + (size_t)cl*K + k0 + q*8;
            cp16(sbase + (uint32_t)((s*STGH + row*AH + q*8)*2), src, gr < M ? 16 : 0);
        }
        #pragma unroll
        for (int i = 0; i < 2; i++){
            int f = tid + i*256;
            int row = f >> 4, q = f & 15;
            const __half* src = B + (size_t)(k0 + row)*N + n0 + q*8;
            cp16(sbase + (uint32_t)((s*STGH + BM*AH + row*BH + q*8)*2), src, 16);
        }
        asm volatile("cp.async.commit_group;" ::: "memory");
    };

    const int nch = K / BK;
    issue(0, 0);
    if (nch > 1) issue(1, 1);
    int s = 0;
    for (int kc = 0; kc < nch; kc++){
        if (kc + 1 < nch){
            asm volatile("cp.async.wait_group 1;" ::: "memory");
        } else {
            asm volatile("cp.async.wait_group 0;" ::: "memory");
        }
        __syncthreads();
        if (kc + 2 < nch){
            int s2 = s + 2; if (s2 >= NSTAGE) s2 -= NSTAGE;
            issue(kc + 2, s2);
        }
        const uint32_t sa = sbase + (uint32_t)(s*STGH)*2;
        const uint32_t sb = sbase + (uint32_t)(s*STGH + BM*AH)*2;
        #pragma unroll
        for (int kk = 0; kk < 2; kk++){
            uint32_t af[2][4];
            #pragma unroll
            for (int mi = 0; mi < 2; mi++)
                ldsm4(af[mi], sa + (uint32_t)(((wm + mi*16 + lr)*AH + kk*16 + lc*8)*2));
            #pragma unroll
            for (int nb = 0; nb < 4; nb++){
                uint32_t bf[4];
                ldsm4t(bf, sb + (uint32_t)(((kk*16 + lr)*BH + wn + nb*16 + lc*8)*2));
                mma16816(acc[0][nb*2+0], af[0], bf[0], bf[1]);
                mma16816(acc[1][nb*2+0], af[1], bf[0], bf[1]);
                mma16816(acc[0][nb*2+1], af[0], bf[2], bf[3]);
                mma16816(acc[1][nb*2+1], af[1], bf[2], bf[3]);
            }
        }
        if (++s >= NSTAGE) s = 0;
    }

    #pragma unroll
    for (int mi = 0; mi < 2; mi++){
        const int r0 = m0 + wm + mi*16 + g;
        #pragma unroll
        for (int half = 0; half < 2; half++){
            const int gr = r0 + half*8;
            if (gr < M){
                #pragma unroll
                for (int ni = 0; ni < 8; ni++){
                    const int col = n0 + wn + ni*8 + t*2;
                    float2 bb = *(const float2*)(bias + col);
                    float v0 = acc[mi][ni][half*2 + 0] + bb.x;
                    float v1 = acc[mi][ni][half*2 + 1] + bb.y;
                    if (EPI == 1){
                        v0 = 0.5f*v0*(1.f + erff(v0*0.70710678118654752f));
                        v1 = 0.5f*v1*(1.f + erff(v1*0.70710678118654752f));
                    }
                    if (EPI == 2){
                        float2 rr = *(const float2*)(Res + (size_t)gr*N + col);
                        v0 += rr.x; v1 += rr.y;
                    }
                    if (sizeof(TOUT) == 2){
                        *(__half2*)((__half*)C + (size_t)gr*N + col) = __floats2half2_rn(v0, v1);
                    } else {
                        *(float2*)((float*)C + (size_t)gr*N + col) = make_float2(v0, v1);
                    }
                }
            }
        }
    }
}

// ---------------- attention via fp16 tensor cores + ldmatrix ----------------
// one block (128 thr, 4 warps) per (window, head); 49 tokens padded to 64.
#define QH 40   // Q/K/V smem row stride (halves) — LDSM conflict-free
#define PH 72   // P smem row stride (halves)     — LDSM conflict-free
__global__ __launch_bounds__(128) void attn_kernel(const float* __restrict__ relt)
{
    __shared__ __half Qs[64][QH];
    __shared__ __half Ks[64][QH];
    __shared__ __half Vs[64][QH];
    __shared__ __half Ps[64][PH];
    __shared__ float  Ss[64][68];

    const int tid = threadIdx.x;
    const int warp = tid >> 5, lane = tid & 31;
    const int g = lane >> 2, t = lane & 3;
    const int lr = lane & 15, lc = lane >> 4;
    const int wh  = blockIdx.x;
    const int win = wh >> 3;
    const int h   = wh & 7;

    // ---- load q,k,v (fp16) into smem; pad rows zeroed
    const __half* base = g_qkvh + (size_t)win*NTOK*(3*DIM) + h*HD;
    for (int e = tid; e < 64*16; e += 128){
        int n = e >> 4, d = e & 15;
        __half2 q, k, v;
        if (n < NTOK){
            const __half2* row = (const __half2*)(base + (size_t)n*(3*DIM));
            q = row[d]; k = row[(DIM>>1) + d]; v = row[DIM + d];
        } else {
            q = __floats2half2_rn(0.f,0.f); k = q; v = q;
        }
        *(__half2*)&Qs[n][d*2] = q;
        *(__half2*)&Ks[n][d*2] = k;
        *(__half2*)&Vs[n][d*2] = v;
    }
    __syncthreads();

    // ---- S = Q @ K^T (both K-major -> non-trans ldsm on both)
    float accs[8][4];
    #pragma unroll
    for (int ni = 0; ni < 8; ni++)
        #pragma unroll
        for (int q = 0; q < 4; q++) accs[ni][q] = 0.f;

    const uint32_t qb = smem_u32(Qs), kb = smem_u32(Ks);
    #pragma unroll
    for (int kk = 0; kk < 2; kk++){
        uint32_t a[4];
        ldsm4(a, qb + (uint32_t)(((16*warp + lr)*QH + kk*16 + lc*8)*2));
        #pragma unroll
        for (int nb = 0; nb < 4; nb++){
            uint32_t b[4];
            ldsm4(b, kb + (uint32_t)(((nb*16 + lr)*QH + kk*16 + lc*8)*2));
            mma16816(accs[nb*2+0], a, b[0], b[2]);
            mma16816(accs[nb*2+1], a, b[1], b[3]);
        }
    }

    // ---- S epilogue: scale + rel-bias + shift mask -> Ss (fp32)
    const int w  = win % NWIN;
    const int wr = w / 9, wc = w - (w/9)*9;
    const float scale = 0.17677669529663687f;   // 1/sqrt(32)
    #pragma unroll
    for (int ni = 0; ni < 8; ni++){
        #pragma unroll
        for (int half = 0; half < 2; half++){
            int row = 16*warp + half*8 + g;
            int c0 = ni*8 + t*2;
            float v0 = accs[ni][half*2 + 0] * scale;
            float v1 = accs[ni][half*2 + 1] * scale;
            if (row < NTOK){
                int in_ = row/7, jn = row - (row/7)*7;
                int rn = region_label(wr*7 + in_)*3 + region_label(wc*7 + jn);
                if (c0 < NTOK){
                    int im = c0/7, jm = c0 - (c0/7)*7;
                    v0 += __ldg(&relt[((in_ - im + 6)*13 + (jn - jm + 6))*NHEAD + h]);
                    int rm = region_label(wr*7 + im)*3 + region_label(wc*7 + jm);
                    if (rn != rm) v0 -= 100.f;
                }
                if (c0 + 1 < NTOK){
                    int c1 = c0 + 1;
                    int im = c1/7, jm = c1 - (c1/7)*7;
                    v1 += __ldg(&relt[((in_ - im + 6)*13 + (jn - jm + 6))*NHEAD + h]);
                    int rm = region_label(wr*7 + im)*3 + region_label(wc*7 + jm);
                    if (rn != rm) v1 -= 100.f;
                }
            }
            Ss[row][c0]     = v0;
            Ss[row][c0 + 1] = v1;
        }
    }
    __syncthreads();

    // ---- softmax (fp32) -> P (fp16)
    if (tid < NTOK){
        float mx = -1e30f;
        #pragma unroll
        for (int m = 0; m < NTOK; m++) mx = fmaxf(mx, Ss[tid][m]);
        float s = 0.f;
        float e[NTOK];
        #pragma unroll
        for (int m = 0; m < NTOK; m++){ e[m] = __expf(Ss[tid][m] - mx); s += e[m]; }
        float inv = 1.f / s;
        #pragma unroll
        for (int m = 0; m < NTOK; m += 2){
            float p0 = e[m]*inv;
            float p1 = (m+1 < NTOK) ? e[m+1]*inv : 0.f;
            *(__half2*)&Ps[tid][m] = __floats2half2_rn(p0, p1);
        }
        #pragma unroll
        for (int m = NTOK+1; m < 64; m += 2)
            *(__half2*)&Ps[tid][m] = __floats2half2_rn(0.f, 0.f);
    } else if (tid >= 64 && tid < 64 + (64 - NTOK)){
        int row = NTOK + (tid - 64);
        #pragma unroll
        for (int m = 0; m < 64; m += 2)
            *(__half2*)&Ps[row][m] = __floats2half2_rn(0.f, 0.f);
    }
    __syncthreads();

    // ---- O = P @ V (P row-major [M][K], V [K][N] -> trans ldsm)
    float acco[4][4];
    #pragma unroll
    for (int ni = 0; ni < 4; ni++)
        #pragma unroll
        for (int q = 0; q < 4; q++) acco[ni][q] = 0.f;

    const uint32_t pb = smem_u32(Ps), vb = smem_u32(Vs);
    #pragma unroll
    for (int kk = 0; kk < 4; kk++){
        uint32_t a[4];
        ldsm4(a, pb + (uint32_t)(((16*warp + lr)*PH + kk*16 + lc*8)*2));
        #pragma unroll
        for (int nb = 0; nb < 2; nb++){
            uint32_t b[4];
            ldsm4t(b, vb + (uint32_t)(((kk*16 + lr)*QH + nb*16 + lc*8)*2));
            mma16816(acco[nb*2+0], a, b[0], b[1]);
            mma16816(acco[nb*2+1], a, b[2], b[3]);
        }
    }

    // ---- write O (fp16)
    __half* out = g_atth + (size_t)win*NTOK*DIM + h*HD;
    #pragma unroll
    for (int ni = 0; ni < 4; ni++){
        #pragma unroll
        for (int half = 0; half < 2; half++){
            int row = 16*warp + half*8 + g;
            if (row < NTOK){
                int col = ni*8 + t*2;
                *(__half2*)(out + (size_t)row*DIM + col) =
                    __floats2half2_rn(acco[ni][half*2 + 0], acco[ni][half*2 + 1]);
            }
        }
    }
}

// ---------------- host launcher ----------------
extern "C" void kernel_launch(void* const* d_in, const int* in_sizes, int n_in,
                              void* d_out, int out_size)
{
    (void)in_sizes; (void)n_in; (void)out_size;
    const float* x      = (const float*)d_in[0];
    const float* g1     = (const float*)d_in[1];
    const float* b1     = (const float*)d_in[2];
    const float* w_qkv  = (const float*)d_in[3];
    const float* b_qkv  = (const float*)d_in[4];
    const float* relt   = (const float*)d_in[5];
    const float* w_proj = (const float*)d_in[6];
    const float* b_proj = (const float*)d_in[7];
    const float* g2     = (const float*)d_in[8];
    const float* b2     = (const float*)d_in[9];
    const float* w_fc1  = (const float*)d_in[10];
    const float* b_fc1  = (const float*)d_in[11];
    const float* w_fc2  = (const float*)d_in[12];
    const float* b_fc2  = (const float*)d_in[13];
    float* out = (float*)d_out;

    __half *p_xh, *p_qkvh, *p_atth, *p_yh, *p_hh, *p_wq, *p_wp, *p_w1, *p_w2;
    float *p_proj, *p_x1;
    cudaGetSymbolAddress((void**)&p_xh,  g_xh);
    cudaGetSymbolAddress((void**)&p_qkvh,g_qkvh);
    cudaGetSymbolAddress((void**)&p_atth,g_atth);
    cudaGetSymbolAddress((void**)&p_proj,g_proj);
    cudaGetSymbolAddress((void**)&p_x1,  g_x1);
    cudaGetSymbolAddress((void**)&p_yh,  g_yh);
    cudaGetSymbolAddress((void**)&p_hh,  g_hh);
    cudaGetSymbolAddress((void**)&p_wq,  g_wq);
    cudaGetSymbolAddress((void**)&p_wp,  g_wp);
    cudaGetSymbolAddress((void**)&p_w1,  g_w1);
    cudaGetSymbolAddress((void**)&p_w2,  g_w2);

    cudaFuncSetAttribute(hgemm<0,__half>, cudaFuncAttributeMaxDynamicSharedMemorySize, GEMM_SMEM);
    cudaFuncSetAttribute(hgemm<0,float>,  cudaFuncAttributeMaxDynamicSharedMemorySize, GEMM_SMEM);
    cudaFuncSetAttribute(hgemm<1,__half>, cudaFuncAttributeMaxDynamicSharedMemorySize, GEMM_SMEM);
    cudaFuncSetAttribute(hgemm<2,float>,  cudaFuncAttributeMaxDynamicSharedMemorySize, GEMM_SMEM);

    // 0) weights -> fp16
    f2h_kernel<<<(256*768/2 + 255)/256, 256>>>(w_qkv, p_wq, 256*768/2);
    f2h_kernel<<<(256*256/2 + 255)/256, 256>>>(w_proj, p_wp, 256*256/2);
    f2h_kernel<<<(256*1024/2 + 255)/256, 256>>>(w_fc1, p_w1, 256*1024/2);
    f2h_kernel<<<(1024*256/2 + 255)/256, 256>>>(w_fc2, p_w2, 1024*256/2);

    // 1) LN1 + pad + shift + window partition (fp16)
    ln1_window_kernel<<<(MW*32 + 255)/256, 256>>>(x, g1, b1);

    // 2) QKV GEMM [MW,256]x[256,768] -> fp16
    hgemm<0,__half><<<dim3(768/BN, (MW + BM - 1)/BM), 256, GEMM_SMEM>>>(
        p_xh, p_wq, b_qkv, (const float*)0, p_qkvh, MW, 768, 256);

    // 3) attention (fp16 MMA) -> fp16
    attn_kernel<<<BATCH*NWIN*NHEAD, 128>>>(relt);

    // 4) proj GEMM [MW,256]x[256,256] -> fp32
    hgemm<0,float><<<dim3(256/BN, (MW + BM - 1)/BM), 256, GEMM_SMEM>>>(
        p_atth, p_wp, b_proj, (const float*)0, p_proj, MW, 256, 256);

    // 5) window reverse + unshift + residual + LN2
    resid_ln2_kernel<<<(MT*32 + 255)/256, 256>>>(x, g2, b2);

    // 6) fc1 + GELU [MT,256]x[256,1024] -> fp16
    hgemm<1,__half><<<dim3(1024/BN, MT/BM), 256, GEMM_SMEM>>>(
        p_yh, p_w1, b_fc1, (const float*)0, p_hh, MT, 1024, 256);

    // 7) fc2 + bias + residual [MT,1024]x[1024,256] -> out fp32
    hgemm<2,float><<<dim3(256/BN, MT/BM), 256, GEMM_SMEM>>>(
        p_hh, p_w2, b_fc2, p_x1, out, MT, 256, 1024);
}

// round 11
// speedup vs baseline: 5.0268x; 1.0431x over previous
#include <cuda_runtime.h>
#include <cuda_fp16.h>
#include <math.h>
#include <stdint.h>

// ---------------- static config ----------------
#define BATCH 24
#define HH 60
#define WW 60
#define HP 63
#define WSZ 7
#define SSZ 3
#define NWIN 81          // 9x9 windows
#define NTOK 49          // tokens per window
#define DIM 256
#define NHEAD 8
#define HD 32
#define MW (BATCH*NWIN*NTOK)   // 95256 window tokens
#define MT (BATCH*HH*WW)       // 86400 real tokens

// GEMM tiling (mma.sync m16n8k16 fp16)
#define BM 128
#define BN 128
#define BK 64
#define AH 72                  // A smem row stride (halves) — LDSM conflict-free
#define BH 136                 // B smem row stride (halves) — LDSM.T conflict-free
#define STGH (BM*AH + BK*BH)   // halves per stage = 9216 + 8704 = 17920
#define NSTAGE 3
#define GEMM_SMEM (NSTAGE*STGH*2)   // 107520 bytes

// ---------------- scratch (static device globals) ----------------
__device__ __half g_xh  [(size_t)MW*DIM];     // LN1 windowed output (fp16)
__device__ __half g_qkvh[(size_t)MW*3*DIM];   // qkv (fp16)
__device__ __half g_atth[(size_t)MW*DIM];     // attention output (fp16)
__device__ __half g_projh[(size_t)MW*DIM];    // proj output (fp16, window layout)
__device__ float  g_x1  [(size_t)MT*DIM];     // x + attn branch (fp32)
__device__ __half g_yh  [(size_t)MT*DIM];     // LN2 output (fp16)
__device__ __half g_hh  [(size_t)MT*4*DIM];   // fc1 output (fp16)
// fp16 weights
__device__ __half g_wq[256*768];
__device__ __half g_wp[256*256];
__device__ __half g_w1[256*1024];
__device__ __half g_w2[1024*256];

// ---------------- helpers ----------------
__device__ __forceinline__ uint32_t smem_u32(const void* p){
    return (uint32_t)__cvta_generic_to_shared((void*)p);
}
__device__ __forceinline__ void ldsm4(uint32_t* r, uint32_t addr){
    asm volatile("ldmatrix.sync.aligned.m8n8.x4.shared.b16 {%0,%1,%2,%3}, [%4];"
        : "=r"(r[0]),"=r"(r[1]),"=r"(r[2]),"=r"(r[3]) : "r"(addr));
}
__device__ __forceinline__ void ldsm4t(uint32_t* r, uint32_t addr){
    asm volatile("ldmatrix.sync.aligned.m8n8.x4.trans.shared.b16 {%0,%1,%2,%3}, [%4];"
        : "=r"(r[0]),"=r"(r[1]),"=r"(r[2]),"=r"(r[3]) : "r"(addr));
}
__device__ __forceinline__ void mma16816(float* c, const uint32_t* a, uint32_t b0, uint32_t b1){
    asm volatile("mma.sync.aligned.m16n8k16.row.col.f32.f16.f16.f32 "
        "{%0,%1,%2,%3}, {%4,%5,%6,%7}, {%8,%9}, {%0,%1,%2,%3};"
        : "+f"(c[0]),"+f"(c[1]),"+f"(c[2]),"+f"(c[3])
        : "r"(a[0]),"r"(a[1]),"r"(a[2]),"r"(a[3]), "r"(b0),"r"(b1));
}
__device__ __forceinline__ void cp16(uint32_t saddr, const void* g, int sz){
    asm volatile("cp.async.cg.shared.global [%0], [%1], 16, %2;"
                 :: "r"(saddr), "l"(g), "r"(sz) : "memory");
}
__device__ __forceinline__ float warp_sum(float v){
    #pragma unroll
    for (int o = 16; o; o >>= 1) v += __shfl_xor_sync(0xffffffffu, v, o);
    return v;
}
__device__ __forceinline__ int region_label(int p){
    return p < (HP - WSZ) ? 0 : (p < (HP - SSZ) ? 1 : 2);
}

// ---------------- fp32 -> fp16 weight conversion ----------------
__global__ void f2h_kernel(const float* __restrict__ s, __half* __restrict__ d, int n2){
    int i = blockIdx.x*blockDim.x + threadIdx.x;
    if (i < n2){
        float2 v = ((const float2*)s)[i];
        ((__half2*)d)[i] = __floats2half2_rn(v.x, v.y);
    }
}

// ---------------- LN1 + pad + shift + window partition (fp16 out) ----------------
__global__ __launch_bounds__(256) void ln1_window_kernel(
    const float* __restrict__ x, const float* __restrict__ g, const float* __restrict__ b)
{
    int warp = (blockIdx.x * blockDim.x + threadIdx.x) >> 5;
    int lane = threadIdx.x & 31;
    if (warp >= MW) return;
    int bi  = warp / (NWIN*NTOK);
    int rem = warp - bi*(NWIN*NTOK);
    int w = rem / NTOK, n = rem - w*NTOK;
    int r = w/9, c = w - r*9, i = n/7, j = n - i*7;
    int hs = r*7 + i + SSZ; if (hs >= HP) hs -= HP;
    int ws = c*7 + j + SSZ; if (ws >= HP) ws -= HP;

    __half2* dst = (__half2*)(g_xh + (size_t)warp*DIM);
    if (hs >= HH || ws >= WW) {
        __half2 z = __floats2half2_rn(0.f, 0.f);
        dst[lane*2] = z; dst[lane*2+1] = z;
        dst[64+lane*2] = z; dst[64+lane*2+1] = z;
        return;
    }
    const float4* src = (const float4*)(x + ((size_t)bi*(HH*WW) + hs*WW + ws)*DIM);
    float4 v0 = src[lane], v1 = src[lane+32];
    float s  = v0.x+v0.y+v0.z+v0.w + v1.x+v1.y+v1.z+v1.w;
    float ss = v0.x*v0.x+v0.y*v0.y+v0.z*v0.z+v0.w*v0.w
             + v1.x*v1.x+v1.y*v1.y+v1.z*v1.z+v1.w*v1.w;
    s  = warp_sum(s);
    ss = warp_sum(ss);
    float mu   = s * (1.f/DIM);
    float var  = ss * (1.f/DIM) - mu*mu;
    float rstd = rsqrtf(var + 1e-5f);
    const float4* gv = (const float4*)g;
    const float4* bv = (const float4*)b;
    float4 g0 = gv[lane], g1 = gv[lane+32], b0 = bv[lane], b1 = bv[lane+32];
    dst[lane*2]      = __floats2half2_rn((v0.x-mu)*rstd*g0.x + b0.x, (v0.y-mu)*rstd*g0.y + b0.y);
    dst[lane*2+1]    = __floats2half2_rn((v0.z-mu)*rstd*g0.z + b0.z, (v0.w-mu)*rstd*g0.w + b0.w);
    dst[64+lane*2]   = __floats2half2_rn((v1.x-mu)*rstd*g1.x + b1.x, (v1.y-mu)*rstd*g1.y + b1.y);
    dst[64+lane*2+1] = __floats2half2_rn((v1.z-mu)*rstd*g1.z + b1.z, (v1.w-mu)*rstd*g1.w + b1.w);
}

// ---------------- window reverse + unshift + residual + LN2 (fused) ----------------
__global__ __launch_bounds__(256) void resid_ln2_kernel(
    const float* __restrict__ x, const float* __restrict__ g, const float* __restrict__ b)
{
    int warp = (blockIdx.x * blockDim.x + threadIdx.x) >> 5;
    int lane = threadIdx.x & 31;
    if (warp >= MT) return;
    int bi = warp / (HH*WW), l = warp - bi*(HH*WW);
    int hh = l / WW, ww = l - hh*WW;
    int hs = hh + (HP - SSZ); if (hs >= HP) hs -= HP;
    int ws = ww + (HP - SSZ); if (ws >= HP) ws -= HP;
    int r = hs/7, i = hs - r*7, c = ws/7, j = ws - c*7;
    size_t m = ((size_t)bi*NWIN + r*9 + c)*NTOK + i*7 + j;

    const float4* xs = (const float4*)(x + (size_t)warp*DIM);
    const __half2* ps = (const __half2*)(g_projh + m*DIM);
    float4 a0 = xs[lane], a1 = xs[lane+32];
    __half2 h0 = ps[lane*2], h1 = ps[lane*2+1], h2 = ps[64+lane*2], h3 = ps[64+lane*2+1];
    float2 f0 = __half22float2(h0), f1 = __half22float2(h1);
    float2 f2 = __half22float2(h2), f3 = __half22float2(h3);
    a0.x += f0.x; a0.y += f0.y; a0.z += f1.x; a0.w += f1.y;
    a1.x += f2.x; a1.y += f2.y; a1.z += f3.x; a1.w += f3.y;
    float4* x1 = (float4*)(g_x1 + (size_t)warp*DIM);
    x1[lane] = a0; x1[lane+32] = a1;

    float s  = a0.x+a0.y+a0.z+a0.w + a1.x+a1.y+a1.z+a1.w;
    float ss = a0.x*a0.x+a0.y*a0.y+a0.z*a0.z+a0.w*a0.w
             + a1.x*a1.x+a1.y*a1.y+a1.z*a1.z+a1.w*a1.w;
    s  = warp_sum(s);
    ss = warp_sum(ss);
    float mu   = s * (1.f/DIM);
    float var  = ss * (1.f/DIM) - mu*mu;
    float rstd = rsqrtf(var + 1e-5f);
    const float4* gv = (const float4*)g;
    const float4* bv = (const float4*)b;
    float4 g0 = gv[lane], g1 = gv[lane+32], b0 = bv[lane], b1 = bv[lane+32];
    __half2* dst = (__half2*)(g_yh + (size_t)warp*DIM);
    dst[lane*2]      = __floats2half2_rn((a0.x-mu)*rstd*g0.x + b0.x, (a0.y-mu)*rstd*g0.y + b0.y);
    dst[lane*2+1]    = __floats2half2_rn((a0.z-mu)*rstd*g0.z + b0.z, (a0.w-mu)*rstd*g0.w + b0.w);
    dst[64+lane*2]   = __floats2half2_rn((a1.x-mu)*rstd*g1.x + b1.x, (a1.y-mu)*rstd*g1.y + b1.y);
    dst[64+lane*2+1] = __floats2half2_rn((a1.z-mu)*rstd*g1.z + b1.z, (a1.w-mu)*rstd*g1.w + b1.w);
}

// ---------------- fp16 mma.sync GEMM, BK=64, 3-stage cp.async + ldmatrix ----------------
template<int EPI, typename TOUT>
__global__ __launch_bounds__(256, 2) void hgemm(
    const __half* __restrict__ A, const __half* __restrict__ B,
    const float* __restrict__ bias, const float* __restrict__ Res,
    TOUT* __restrict__ C, int M, int N, int K)
{
    extern __shared__ __half sm[];
    const int tid = threadIdx.x;
    const int m0 = blockIdx.y * BM, n0 = blockIdx.x * BN;
    const int lane = tid & 31, warp = tid >> 5;
    const int wm = (warp >> 1) * 32;     // 4 warps along M
    const int wn = (warp & 1) * 64;      // 2 warps along N
    const int g = lane >> 2, t = lane & 3;
    const int lr = lane & 15, lc = lane >> 4;

    float acc[2][8][4];
    #pragma unroll
    for (int mi = 0; mi < 2; mi++)
        #pragma unroll
        for (int ni = 0; ni < 8; ni++)
            #pragma unroll
            for (int q = 0; q < 4; q++) acc[mi][ni][q] = 0.f;

    const uint32_t sbase = smem_u32(sm);

    auto issue = [&](int kc, int s){
        const int k0 = kc * BK;
        // A tile: 128 rows x 64 halves = 8 x 16B chunks/row
        #pragma unroll
        for (int i = 0; i < 4; i++){
            int f = tid + i*256;
            int row = f >> 3, q = f & 7;
            int gr = m0 + row;
            int cl = gr < M ? gr : (M - 1);
            const __half* src = A + (size_t)cl*K + k0 + q*8;
            cp16(sbase + (uint32_t)((s*STGH + row*AH + q*8)*2), src, gr < M ? 16 : 0);
        }
        // B tile: 64 rows x 128 halves = 16 x 16B chunks/row
        #pragma unroll
        for (int i = 0; i < 4; i++){
            int f = tid + i*256;
            int row = f >> 4, q = f & 15;
            const __half* src = B + (size_t)(k0 + row)*N + n0 + q*8;
            cp16(sbase + (uint32_t)((s*STGH + BM*AH + row*BH + q*8)*2), src, 16);
        }
        asm volatile("cp.async.commit_group;" ::: "memory");
    };

    const int nch = K / BK;
    issue(0, 0);
    if (nch > 1) issue(1, 1);
    int s = 0;
    for (int kc = 0; kc < nch; kc++){
        if (kc + 1 < nch){
            asm volatile("cp.async.wait_group 1;" ::: "memory");
        } else {
            asm volatile("cp.async.wait_group 0;" ::: "memory");
        }
        __syncthreads();
        if (kc + 2 < nch){
            int s2 = s + 2; if (s2 >= NSTAGE) s2 -= NSTAGE;
            issue(kc + 2, s2);
        }
        const uint32_t sa = sbase + (uint32_t)(s*STGH)*2;
        const uint32_t sb = sbase + (uint32_t)(s*STGH + BM*AH)*2;
        #pragma unroll
        for (int kk = 0; kk < 4; kk++){
            uint32_t af[2][4];
            #pragma unroll
            for (int mi = 0; mi < 2; mi++)
                ldsm4(af[mi], sa + (uint32_t)(((wm + mi*16 + lr)*AH + kk*16 + lc*8)*2));
            #pragma unroll
            for (int nb = 0; nb < 4; nb++){
                uint32_t bf[4];
                ldsm4t(bf, sb + (uint32_t)(((kk*16 + lr)*BH + wn + nb*16 + lc*8)*2));
                mma16816(acc[0][nb*2+0], af[0], bf[0], bf[1]);
                mma16816(acc[1][nb*2+0], af[1], bf[0], bf[1]);
                mma16816(acc[0][nb*2+1], af[0], bf[2], bf[3]);
                mma16816(acc[1][nb*2+1], af[1], bf[2], bf[3]);
            }
        }
        if (++s >= NSTAGE) s = 0;
    }

    #pragma unroll
    for (int mi = 0; mi < 2; mi++){
        const int r0 = m0 + wm + mi*16 + g;
        #pragma unroll
        for (int half = 0; half < 2; half++){
            const int gr = r0 + half*8;
            if (gr < M){
                #pragma unroll
                for (int ni = 0; ni < 8; ni++){
                    const int col = n0 + wn + ni*8 + t*2;
                    float2 bb = *(const float2*)(bias + col);
                    float v0 = acc[mi][ni][half*2 + 0] + bb.x;
                    float v1 = acc[mi][ni][half*2 + 1] + bb.y;
                    if (EPI == 1){
                        v0 = 0.5f*v0*(1.f + erff(v0*0.70710678118654752f));
                        v1 = 0.5f*v1*(1.f + erff(v1*0.70710678118654752f));
                    }
                    if (EPI == 2){
                        float2 rr = *(const float2*)(Res + (size_t)gr*N + col);
                        v0 += rr.x; v1 += rr.y;
                    }
                    if (sizeof(TOUT) == 2){
                        *(__half2*)((__half*)C + (size_t)gr*N + col) = __floats2half2_rn(v0, v1);
                    } else {
                        *(float2*)((float*)C + (size_t)gr*N + col) = make_float2(v0, v1);
                    }
                }
            }
        }
    }
}

// ---------------- attention via fp16 tensor cores + ldmatrix ----------------
#define QH 40   // Q/K/V smem row stride (halves) — LDSM conflict-free
#define PH 72   // P smem row stride (halves)     — LDSM conflict-free
__global__ __launch_bounds__(128) void attn_kernel(const float* __restrict__ relt)
{
    __shared__ __half Qs[64][QH];
    __shared__ __half Ks[64][QH];
    __shared__ __half Vs[64][QH];
    __shared__ __half Ps[64][PH];
    __shared__ float  Ss[64][68];

    const int tid = threadIdx.x;
    const int warp = tid >> 5, lane = tid & 31;
    const int g = lane >> 2, t = lane & 3;
    const int lr = lane & 15, lc = lane >> 4;
    const int wh  = blockIdx.x;
    const int win = wh >> 3;
    const int h   = wh & 7;

    const __half* base = g_qkvh + (size_t)win*NTOK*(3*DIM) + h*HD;
    for (int e = tid; e < 64*16; e += 128){
        int n = e >> 4, d = e & 15;
        __half2 q, k, v;
        if (n < NTOK){
            const __half2* row = (const __half2*)(base + (size_t)n*(3*DIM));
            q = row[d]; k = row[(DIM>>1) + d]; v = row[DIM + d];
        } else {
            q = __floats2half2_rn(0.f,0.f); k = q; v = q;
        }
        *(__half2*)&Qs[n][d*2] = q;
        *(__half2*)&Ks[n][d*2] = k;
        *(__half2*)&Vs[n][d*2] = v;
    }
    __syncthreads();

    float accs[8][4];
    #pragma unroll
    for (int ni = 0; ni < 8; ni++)
        #pragma unroll
        for (int q = 0; q < 4; q++) accs[ni][q] = 0.f;

    const uint32_t qb = smem_u32(Qs), kb = smem_u32(Ks);
    #pragma unroll
    for (int kk = 0; kk < 2; kk++){
        uint32_t a[4];
        ldsm4(a, qb + (uint32_t)(((16*warp + lr)*QH + kk*16 + lc*8)*2));
        #pragma unroll
        for (int nb = 0; nb < 4; nb++){
            uint32_t b[4];
            ldsm4(b, kb + (uint32_t)(((nb*16 + lr)*QH + kk*16 + lc*8)*2));
            mma16816(accs[nb*2+0], a, b[0], b[2]);
            mma16816(accs[nb*2+1], a, b[1], b[3]);
        }
    }

    const int w  = win % NWIN;
    const int wr = w / 9, wc = w - (w/9)*9;
    const float scale = 0.17677669529663687f;   // 1/sqrt(32)
    #pragma unroll
    for (int ni = 0; ni < 8; ni++){
        #pragma unroll
        for (int half = 0; half < 2; half++){
            int row = 16*warp + half*8 + g;
            int c0 = ni*8 + t*2;
            float v0 = accs[ni][half*2 + 0] * scale;
            float v1 = accs[ni][half*2 + 1] * scale;
            if (row < NTOK){
                int in_ = row/7, jn = row - (row/7)*7;
                int rn = region_label(wr*7 + in_)*3 + region_label(wc*7 + jn);
                if (c0 < NTOK){
                    int im = c0/7, jm = c0 - (c0/7)*7;
                    v0 += __ldg(&relt[((in_ - im + 6)*13 + (jn - jm + 6))*NHEAD + h]);
                    int rm = region_label(wr*7 + im)*3 + region_label(wc*7 + jm);
                    if (rn != rm) v0 -= 100.f;
                }
                if (c0 + 1 < NTOK){
                    int c1 = c0 + 1;
                    int im = c1/7, jm = c1 - (c1/7)*7;
                    v1 += __ldg(&relt[((in_ - im + 6)*13 + (jn - jm + 6))*NHEAD + h]);
                    int rm = region_label(wr*7 + im)*3 + region_label(wc*7 + jm);
                    if (rn != rm) v1 -= 100.f;
                }
            }
            Ss[row][c0]     = v0;
            Ss[row][c0 + 1] = v1;
        }
    }
    __syncthreads();

    if (tid < NTOK){
        float mx = -1e30f;
        #pragma unroll
        for (int m = 0; m < NTOK; m++) mx = fmaxf(mx, Ss[tid][m]);
        float s = 0.f;
        float e[NTOK];
        #pragma unroll
        for (int m = 0; m < NTOK; m++){ e[m] = __expf(Ss[tid][m] - mx); s += e[m]; }
        float inv = 1.f / s;
        #pragma unroll
        for (int m = 0; m < NTOK; m += 2){
            float p0 = e[m]*inv;
            float p1 = (m+1 < NTOK) ? e[m+1]*inv : 0.f;
            *(__half2*)&Ps[tid][m] = __floats2half2_rn(p0, p1);
        }
        #pragma unroll
        for (int m = NTOK+1; m < 64; m += 2)
            *(__half2*)&Ps[tid][m] = __floats2half2_rn(0.f, 0.f);
    } else if (tid >= 64 && tid < 64 + (64 - NTOK)){
        int row = NTOK + (tid - 64);
        #pragma unroll
        for (int m = 0; m < 64; m += 2)
            *(__half2*)&Ps[row][m] = __floats2half2_rn(0.f, 0.f);
    }
    __syncthreads();

    float acco[4][4];
    #pragma unroll
    for (int ni = 0; ni < 4; ni++)
        #pragma unroll
        for (int q = 0; q < 4; q++) acco[ni][q] = 0.f;

    const uint32_t pb = smem_u32(Ps), vb = smem_u32(Vs);
    #pragma unroll
    for (int kk = 0; kk < 4; kk++){
        uint32_t a[4];
        ldsm4(a, pb + (uint32_t)(((16*warp + lr)*PH + kk*16 + lc*8)*2));
        #pragma unroll
        for (int nb = 0; nb < 2; nb++){
            uint32_t b[4];
            ldsm4t(b, vb + (uint32_t)(((kk*16 + lr)*QH + nb*16 + lc*8)*2));
            mma16816(acco[nb*2+0], a, b[0], b[1]);
            mma16816(acco[nb*2+1], a, b[2], b[3]);
        }
    }

    __half* out = g_atth + (size_t)win*NTOK*DIM + h*HD;
    #pragma unroll
    for (int ni = 0; ni < 4; ni++){
        #pragma unroll
        for (int half = 0; half < 2; half++){
            int row = 16*warp + half*8 + g;
            if (row < NTOK){
                int col = ni*8 + t*2;
                *(__half2*)(out + (size_t)row*DIM + col) =
                    __floats2half2_rn(acco[ni][half*2 + 0], acco[ni][half*2 + 1]);
            }
        }
    }
}

// ---------------- host launcher ----------------
extern "C" void kernel_launch(void* const* d_in, const int* in_sizes, int n_in,
                              void* d_out, int out_size)
{
    (void)in_sizes; (void)n_in; (void)out_size;
    const float* x      = (const float*)d_in[0];
    const float* g1     = (const float*)d_in[1];
    const float* b1     = (const float*)d_in[2];
    const float* w_qkv  = (const float*)d_in[3];
    const float* b_qkv  = (const float*)d_in[4];
    const float* relt   = (const float*)d_in[5];
    const float* w_proj = (const float*)d_in[6];
    const float* b_proj = (const float*)d_in[7];
    const float* g2     = (const float*)d_in[8];
    const float* b2     = (const float*)d_in[9];
    const float* w_fc1  = (const float*)d_in[10];
    const float* b_fc1  = (const float*)d_in[11];
    const float* w_fc2  = (const float*)d_in[12];
    const float* b_fc2  = (const float*)d_in[13];
    float* out = (float*)d_out;

    __half *p_xh, *p_qkvh, *p_atth, *p_projh, *p_yh, *p_hh, *p_wq, *p_wp, *p_w1, *p_w2;
    float *p_x1;
    cudaGetSymbolAddress((void**)&p_xh,  g_xh);
    cudaGetSymbolAddress((void**)&p_qkvh,g_qkvh);
    cudaGetSymbolAddress((void**)&p_atth,g_atth);
    cudaGetSymbolAddress((void**)&p_projh,g_projh);
    cudaGetSymbolAddress((void**)&p_x1,  g_x1);
    cudaGetSymbolAddress((void**)&p_yh,  g_yh);
    cudaGetSymbolAddress((void**)&p_hh,  g_hh);
    cudaGetSymbolAddress((void**)&p_wq,  g_wq);
    cudaGetSymbolAddress((void**)&p_wp,  g_wp);
    cudaGetSymbolAddress((void**)&p_w1,  g_w1);
    cudaGetSymbolAddress((void**)&p_w2,  g_w2);

    cudaFuncSetAttribute(hgemm<0,__half>, cudaFuncAttributeMaxDynamicSharedMemorySize, GEMM_SMEM);
    cudaFuncSetAttribute(hgemm<1,__half>, cudaFuncAttributeMaxDynamicSharedMemorySize, GEMM_SMEM);
    cudaFuncSetAttribute(hgemm<2,float>,  cudaFuncAttributeMaxDynamicSharedMemorySize, GEMM_SMEM);

    // 0) weights -> fp16
    f2h_kernel<<<(256*768/2 + 255)/256, 256>>>(w_qkv, p_wq, 256*768/2);
    f2h_kernel<<<(256*256/2 + 255)/256, 256>>>(w_proj, p_wp, 256*256/2);
    f2h_kernel<<<(256*1024/2 + 255)/256, 256>>>(w_fc1, p_w1, 256*1024/2);
    f2h_kernel<<<(1024*256/2 + 255)/256, 256>>>(w_fc2, p_w2, 1024*256/2);

    // 1) LN1 + pad + shift + window partition (fp16)
    ln1_window_kernel<<<(MW*32 + 255)/256, 256>>>(x, g1, b1);

    // 2) QKV GEMM [MW,256]x[256,768] -> fp16
    hgemm<0,__half><<<dim3(768/BN, (MW + BM - 1)/BM), 256, GEMM_SMEM>>>(
        p_xh, p_wq, b_qkv, (const float*)0, p_qkvh, MW, 768, 256);

    // 3) attention (fp16 MMA) -> fp16
    attn_kernel<<<BATCH*NWIN*NHEAD, 128>>>(relt);

    // 4) proj GEMM [MW,256]x[256,256] -> fp16
    hgemm<0,__half><<<dim3(256/BN, (MW + BM - 1)/BM), 256, GEMM_SMEM>>>(
        p_atth, p_wp, b_proj, (const float*)0, p_projh, MW, 256, 256);

    // 5) window reverse + unshift + residual + LN2
    resid_ln2_kernel<<<(MT*32 + 255)/256, 256>>>(x, g2, b2);

    // 6) fc1 + GELU [MT,256]x[256,1024] -> fp16
    hgemm<1,__half><<<dim3(1024/BN, MT/BM), 256, GEMM_SMEM>>>(
        p_yh, p_w1, b_fc1, (const float*)0, p_hh, MT, 1024, 256);

    // 7) fc2 + bias + residual [MT,1024]x[1024,256] -> out fp32
    hgemm<2,float><<<dim3(256/BN, MT/BM), 256, GEMM_SMEM>>>(
        p_hh, p_w2, b_fc2, p_x1, out, MT, 256, 1024);
}